// round 9
// baseline (speedup 1.0000x reference)
#include <cuda_runtime.h>
#include <math.h>

#define BQ   512
#define TQ   1024
#define DQ   4
#define HQ   64
#define G4   256          // 4*H
#define NB   8            // batches per recurrent block (one block per SM)
#define NCLS 1098
#define FB   8            // batches per final-head block

#define HX_STRIDE 76      // [h(64) | x(4) | 1 | 0..]; 76 -> conflict-free B-frag LDS
#define GP_STRIDE 10      // gpre[gate][batch(8)] stride, float2-aligned

// ---------------- scratch (static device allocations only) ----------------
__device__ float g_g1[2][(size_t)BQ * TQ * G4];   // layer-1 gate preactivations per dir
__device__ float g_h0[(size_t)BQ * TQ * 128];     // layer-0 bidir output, [B][T][128]
__device__ float g_h1last[BQ * 128];              // gathered last timestep of layer 1

// ---------------- helpers ----------------
__device__ __forceinline__ float tanh_fast(float x) {
    float y; asm("tanh.approx.f32 %0,%1;" : "=f"(y) : "f"(x)); return y;
}
__device__ __forceinline__ float sig_fast(float x) {
    return fmaf(0.5f, tanh_fast(0.5f * x), 0.5f);
}
__device__ __forceinline__ unsigned tf32_rna(float v) {
    unsigned y; asm("cvt.rna.tf32.f32 %0,%1;" : "=r"(y) : "f"(v)); return y;
}
__device__ __forceinline__ void mma_tf32(float* c, const unsigned* a, unsigned b0, unsigned b1) {
    asm volatile(
        "mma.sync.aligned.m16n8k8.row.col.f32.tf32.tf32.f32 "
        "{%0,%1,%2,%3},{%4,%5,%6,%7},{%8,%9},{%0,%1,%2,%3};"
        : "+f"(c[0]), "+f"(c[1]), "+f"(c[2]), "+f"(c[3])
        : "r"(a[0]), "r"(a[1]), "r"(a[2]), "r"(a[3]), "r"(b0), "r"(b1));
}

// =====================================================================
// Layer 0: bidirectional LSTM; recurrent matvec on tensor cores.
// D[256 gates, 8 batches] = A[256 x 72] . B[72 x 8]
//   A rows = [Whh | Wih | bias | 0..] (reg-resident tf32 frags)
//   B cols = hx[batch] = [h | x | 1 | 0..] (smem, rebuilt per step)
// One block per SM (128 blocks); all 8 MMA N-columns are real batches.
// Phase B: each thread owns units (pb_b, pb_j) and (pb_b+4, pb_j).
// =====================================================================
__global__ void __launch_bounds__(256, 1)
lstm_l0_kernel(const float* __restrict__ x, const int* __restrict__ lens,
               const float* __restrict__ WihF, const float* __restrict__ WhhF,
               const float* __restrict__ bihF, const float* __restrict__ bhhF,
               const float* __restrict__ WihB, const float* __restrict__ WhhB,
               const float* __restrict__ bihB, const float* __restrict__ bhhB)
{
    const int dir   = blockIdx.x & 1;
    const int xb    = blockIdx.x >> 1;
    const int bbase = xb * NB;
    const int tid  = threadIdx.x;
    const int w    = tid >> 5;
    const int lane = tid & 31;
    const int gid  = lane >> 2;               // 0..7 (MMA row group / B column)
    const int tig  = lane & 3;                // 0..3

    const float* Wih = dir ? WihB : WihF;
    const float* Whh = dir ? WhhB : WhhF;
    const float* bih = dir ? bihB : bihF;
    const float* bhh = dir ? bhhB : bhhF;

    // ---- A fragments: [mt][kc][4], gates on M, K = 72 augmented
    unsigned afr[2][9][4];
#pragma unroll
    for (int mt = 0; mt < 2; ++mt) {
#pragma unroll
        for (int kc = 0; kc < 9; ++kc) {
#pragma unroll
            for (int e = 0; e < 4; ++e) {
                int g = w * 32 + mt * 16 + gid + ((e & 1) ? 8 : 0);
                int k = kc * 8 + tig + ((e & 2) ? 4 : 0);
                float v;
                if (k < 64)       v = Whh[g * HQ + k];
                else if (k < 68)  v = Wih[g * DQ + (k - 64)];
                else if (k == 68) v = bih[g] + bhh[g];
                else              v = 0.0f;
                afr[mt][kc][e] = tf32_rna(v);
            }
        }
    }

    __shared__ float hx[NB][HX_STRIDE];
    __shared__ float gpre[G4 * GP_STRIDE];
    __shared__ int   lsh[NB];

    const int pb_b = tid >> 6;                // 0..3 (second unit: +4)
    const int pb_j = tid & 63;

    if (tid < NB) lsh[tid] = lens[bbase + tid];
    hx[pb_b][pb_j]     = 0.0f;
    hx[pb_b + 4][pb_j] = 0.0f;
    if (tid < NB) {
        hx[tid][68] = 1.0f;
        hx[tid][69] = 0.0f; hx[tid][70] = 0.0f; hx[tid][71] = 0.0f;
    }
    float c0 = 0.0f, c1 = 0.0f;
    __syncthreads();

    const int maxlen = lsh[0];                // lens sorted descending

    if (tid < NB) {
        int len = lsh[tid];
        int tt  = dir ? (len - 1) : 0;
        float4 xv = reinterpret_cast<const float4*>(x)[(size_t)(bbase + tid) * TQ + tt];
        hx[tid][64] = xv.x; hx[tid][65] = xv.y; hx[tid][66] = xv.z; hx[tid][67] = xv.w;
    }
    __syncthreads();

    const float* hxb = &hx[gid][0];

    for (int t = 0; t < maxlen; ++t) {
        // prefetch x(t+1) into regs (overlaps MMA)
        float4 xn = make_float4(0.f, 0.f, 0.f, 0.f);
        if (tid < NB) {
            int tn  = (t + 1 < maxlen) ? (t + 1) : t;
            int len = lsh[tid];
            int tt  = tn;
            if (dir) tt = (tn < len) ? (len - 1 - tn) : tn;
            xn = reinterpret_cast<const float4*>(x)[(size_t)(bbase + tid) * TQ + tt];
        }

        // ---- phase A: tensor-core matvec, split accumulator chains
        float a0[4] = {0.f, 0.f, 0.f, 0.f}, a1[4] = {0.f, 0.f, 0.f, 0.f};
        float e0[4] = {0.f, 0.f, 0.f, 0.f}, e1[4] = {0.f, 0.f, 0.f, 0.f};
#pragma unroll
        for (int kc = 0; kc < 9; kc += 2) {
            unsigned p = __float_as_uint(hxb[kc * 8 + tig]);
            unsigned q = __float_as_uint(hxb[kc * 8 + 4 + tig]);
            mma_tf32(a0, afr[0][kc], p, q);
            mma_tf32(a1, afr[1][kc], p, q);
        }
#pragma unroll
        for (int kc = 1; kc < 9; kc += 2) {
            unsigned p = __float_as_uint(hxb[kc * 8 + tig]);
            unsigned q = __float_as_uint(hxb[kc * 8 + 4 + tig]);
            mma_tf32(e0, afr[0][kc], p, q);
            mma_tf32(e1, afr[1][kc], p, q);
        }
#pragma unroll
        for (int e = 0; e < 4; ++e) { a0[e] += e0[e]; a1[e] += e1[e]; }

        {
            int g0 = w * 32 + gid;
            *reinterpret_cast<float2*>(&gpre[g0 * GP_STRIDE + 2 * tig]) =
                make_float2(a0[0], a0[1]);
            *reinterpret_cast<float2*>(&gpre[(g0 + 8) * GP_STRIDE + 2 * tig]) =
                make_float2(a0[2], a0[3]);
            *reinterpret_cast<float2*>(&gpre[(g0 + 16) * GP_STRIDE + 2 * tig]) =
                make_float2(a1[0], a1[1]);
            *reinterpret_cast<float2*>(&gpre[(g0 + 24) * GP_STRIDE + 2 * tig]) =
                make_float2(a1[2], a1[3]);
        }
        __syncthreads();

        // ---- phase B: two units per thread
#pragma unroll
        for (int uu = 0; uu < 2; ++uu) {
            int bb = pb_b + 4 * uu;
            float& c = uu ? c1 : c0;
            float gi = gpre[(pb_j)       * GP_STRIDE + bb];
            float gf = gpre[(64  + pb_j) * GP_STRIDE + bb];
            float gc = gpre[(128 + pb_j) * GP_STRIDE + bb];
            float go = gpre[(192 + pb_j) * GP_STRIDE + bb];
            float si = sig_fast(gi);
            float sf = sig_fast(gf);
            float tg = tanh_fast(gc);
            float so = sig_fast(go);
            c = sf * c + si * tg;
            float h = so * tanh_fast(c);
            hx[bb][pb_j] = h;

            int len = lsh[bb];
            int ts  = t;
            if (dir) ts = (t < len) ? (len - 1 - t) : t;
            g_h0[((size_t)(bbase + bb) * TQ + ts) * 128 + dir * HQ + pb_j] = h;
        }
        if (tid < NB) {
            hx[tid][64] = xn.x; hx[tid][65] = xn.y;
            hx[tid][66] = xn.z; hx[tid][67] = xn.w;
        }
        __syncthreads();
    }
}

// =====================================================================
// Layer-1 gate GEMM on tensor cores (R7, unchanged).
// =====================================================================
#define GM_ROWS   64
#define AS_STRIDE 132
#define WS_STRIDE 36
#define GEMM_SMEM ((64 * AS_STRIDE + 256 * WS_STRIDE) * 4)   // 70656 B

__global__ void __launch_bounds__(256, 2)
gates1_gemm_kernel(const int* __restrict__ lens,
                   const float* __restrict__ WihF, const float* __restrict__ WihB,
                   const float* __restrict__ bihF, const float* __restrict__ bhhF,
                   const float* __restrict__ bihB, const float* __restrict__ bhhB)
{
    const int tile  = blockIdx.x;
    const int b     = blockIdx.y;
    const int dir   = blockIdx.z;
    const int tbase = tile * GM_ROWS;

    const int len = lens[b];
    if (tbase >= len) return;

    extern __shared__ float sm[];
    float* As = sm;
    float* Ws = sm + 64 * AS_STRIDE;

    const int tid  = threadIdx.x;
    const int lane = tid & 31;
    const int w    = tid >> 5;
    const int wr   = w & 3;
    const int wc   = w >> 2;
    const int gid  = lane >> 2;
    const int tig  = lane & 3;

    const float* Wih = dir ? WihB : WihF;
    const float* bih = dir ? bihB : bihF;
    const float* bhh = dir ? bhhB : bhhF;

    float acc[16][4];
#pragma unroll
    for (int nt = 0; nt < 16; ++nt) {
        int col0 = wc * 128 + nt * 8 + 2 * tig;
        float bv0 = bih[col0]     + bhh[col0];
        float bv1 = bih[col0 + 1] + bhh[col0 + 1];
        acc[nt][0] = bv0; acc[nt][1] = bv1;
        acc[nt][2] = bv0; acc[nt][3] = bv1;
    }

    const float* h0b = g_h0 + (size_t)b * TQ * 128;
#pragma unroll
    for (int i = 0; i < 8; ++i) {
        int idx = tid + 256 * i;
        int r   = idx >> 5, kq = idx & 31;
        int srow = tbase + r;
        if (dir) srow = (srow < len) ? (len - 1 - srow) : srow;
        float4 v = *reinterpret_cast<const float4*>(h0b + (size_t)srow * 128 + 4 * kq);
        *reinterpret_cast<float4*>(&As[r * AS_STRIDE + 4 * kq]) = v;
    }

    const int r0 = wr * 16 + gid;

    for (int k0 = 0; k0 < 128; k0 += 32) {
        __syncthreads();
#pragma unroll
        for (int i = 0; i < 8; ++i) {
            int idx = tid + 256 * i;
            int n   = idx >> 3, kq = idx & 7;
            float4 v = *reinterpret_cast<const float4*>(Wih + (size_t)n * 128 + k0 + 4 * kq);
            *reinterpret_cast<float4*>(&Ws[n * WS_STRIDE + 4 * kq]) = v;
        }
        __syncthreads();

#pragma unroll
        for (int ks = 0; ks < 4; ++ks) {
            const int kl = ks * 8;
            unsigned a[4];
            a[0] = __float_as_uint(As[r0 * AS_STRIDE + k0 + kl + tig]);
            a[1] = __float_as_uint(As[(r0 + 8) * AS_STRIDE + k0 + kl + tig]);
            a[2] = __float_as_uint(As[r0 * AS_STRIDE + k0 + kl + 4 + tig]);
            a[3] = __float_as_uint(As[(r0 + 8) * AS_STRIDE + k0 + kl + 4 + tig]);
#pragma unroll
            for (int nt = 0; nt < 16; ++nt) {
                int n = wc * 128 + nt * 8 + gid;
                unsigned b0 = __float_as_uint(Ws[n * WS_STRIDE + kl + tig]);
                unsigned b1 = __float_as_uint(Ws[n * WS_STRIDE + kl + 4 + tig]);
                mma_tf32(acc[nt], a, b0, b1);
            }
        }
    }

    float* outp = g_g1[dir] + ((size_t)b * TQ + tbase) * G4;
#pragma unroll
    for (int nt = 0; nt < 16; ++nt) {
        int col0 = wc * 128 + nt * 8 + 2 * tig;
        *reinterpret_cast<float2*>(outp + (size_t)r0 * G4 + col0) =
            make_float2(acc[nt][0], acc[nt][1]);
        *reinterpret_cast<float2*>(outp + (size_t)(r0 + 8) * G4 + col0) =
            make_float2(acc[nt][2], acc[nt][3]);
    }
}

// =====================================================================
// Layer 1: recurrent over precomputed gates; h.Whh^T on tensor cores.
// NB=8, one block per SM. Gate preactivations streamed per-unit.
// =====================================================================
__global__ void __launch_bounds__(256, 1)
lstm_l1_kernel(const int* __restrict__ lens,
               const float* __restrict__ WhhF, const float* __restrict__ WhhB)
{
    const int dir   = blockIdx.x & 1;
    const int xb    = blockIdx.x >> 1;
    const int bbase = xb * NB;
    const int tid  = threadIdx.x;
    const int w    = tid >> 5;
    const int lane = tid & 31;
    const int gid  = lane >> 2;
    const int tig  = lane & 3;

    const float* Whh = dir ? WhhB : WhhF;
    const float* gin = g_g1[dir];

    // ---- A fragments: Whh only, K = 64
    unsigned afr[2][8][4];
#pragma unroll
    for (int mt = 0; mt < 2; ++mt) {
#pragma unroll
        for (int kc = 0; kc < 8; ++kc) {
#pragma unroll
            for (int e = 0; e < 4; ++e) {
                int g = w * 32 + mt * 16 + gid + ((e & 1) ? 8 : 0);
                int k = kc * 8 + tig + ((e & 2) ? 4 : 0);
                afr[mt][kc][e] = tf32_rna(Whh[g * HQ + k]);
            }
        }
    }

    __shared__ float hx[NB][HX_STRIDE];
    __shared__ float gpre[G4 * GP_STRIDE];
    __shared__ int   lsh[NB];

    const int pb_b = tid >> 6;
    const int pb_j = tid & 63;
    if (tid < NB) lsh[tid] = lens[bbase + tid];
    hx[pb_b][pb_j]     = 0.0f;
    hx[pb_b + 4][pb_j] = 0.0f;
    float c0 = 0.0f, c1 = 0.0f;
    __syncthreads();

    const int maxlen = lsh[0];
    const float* hxb = &hx[gid][0];

    // per-thread gate-preact streams for both phase-B units
    const float* gsrc0 = gin + (size_t)(bbase + pb_b) * TQ * G4 + pb_j;
    const float* gsrc1 = gin + (size_t)(bbase + pb_b + 4) * TQ * G4 + pb_j;

    float ldc0[4], ldc1[4];
#pragma unroll
    for (int q = 0; q < 4; ++q) { ldc0[q] = gsrc0[q * 64]; ldc1[q] = gsrc1[q * 64]; }

    for (int t = 0; t < maxlen; ++t) {
        float ldn0[4], ldn1[4];
        const int tn = (t + 1 < maxlen) ? (t + 1) : t;
#pragma unroll
        for (int q = 0; q < 4; ++q) {
            ldn0[q] = gsrc0[(size_t)tn * G4 + q * 64];
            ldn1[q] = gsrc1[(size_t)tn * G4 + q * 64];
        }

        // ---- phase A: tensor-core matvec, split chains
        float a0[4] = {0.f, 0.f, 0.f, 0.f}, a1[4] = {0.f, 0.f, 0.f, 0.f};
        float e0[4] = {0.f, 0.f, 0.f, 0.f}, e1[4] = {0.f, 0.f, 0.f, 0.f};
#pragma unroll
        for (int kc = 0; kc < 8; kc += 2) {
            unsigned p = __float_as_uint(hxb[kc * 8 + tig]);
            unsigned q = __float_as_uint(hxb[kc * 8 + 4 + tig]);
            mma_tf32(a0, afr[0][kc], p, q);
            mma_tf32(a1, afr[1][kc], p, q);
        }
#pragma unroll
        for (int kc = 1; kc < 8; kc += 2) {
            unsigned p = __float_as_uint(hxb[kc * 8 + tig]);
            unsigned q = __float_as_uint(hxb[kc * 8 + 4 + tig]);
            mma_tf32(e0, afr[0][kc], p, q);
            mma_tf32(e1, afr[1][kc], p, q);
        }
#pragma unroll
        for (int e = 0; e < 4; ++e) { a0[e] += e0[e]; a1[e] += e1[e]; }

        {
            int g0 = w * 32 + gid;
            *reinterpret_cast<float2*>(&gpre[g0 * GP_STRIDE + 2 * tig]) =
                make_float2(a0[0], a0[1]);
            *reinterpret_cast<float2*>(&gpre[(g0 + 8) * GP_STRIDE + 2 * tig]) =
                make_float2(a0[2], a0[3]);
            *reinterpret_cast<float2*>(&gpre[(g0 + 16) * GP_STRIDE + 2 * tig]) =
                make_float2(a1[0], a1[1]);
            *reinterpret_cast<float2*>(&gpre[(g0 + 24) * GP_STRIDE + 2 * tig]) =
                make_float2(a1[2], a1[3]);
        }
        __syncthreads();

        // ---- phase B: two units per thread
#pragma unroll
        for (int uu = 0; uu < 2; ++uu) {
            int bb = pb_b + 4 * uu;
            float& c = uu ? c1 : c0;
            const float* ld = uu ? ldc1 : ldc0;
            float gi = gpre[(pb_j)       * GP_STRIDE + bb] + ld[0];
            float gf = gpre[(64  + pb_j) * GP_STRIDE + bb] + ld[1];
            float gc = gpre[(128 + pb_j) * GP_STRIDE + bb] + ld[2];
            float go = gpre[(192 + pb_j) * GP_STRIDE + bb] + ld[3];
            float si = sig_fast(gi);
            float sf = sig_fast(gf);
            float tg = tanh_fast(gc);
            float so = sig_fast(go);
            c = sf * c + si * tg;
            float h = so * tanh_fast(c);
            hx[bb][pb_j] = h;

            int  len = lsh[bb];
            bool wr  = dir ? (t == 0) : (t == len - 1);
            if (wr)
                g_h1last[(bbase + bb) * 128 + dir * HQ + pb_j] = h;
        }
#pragma unroll
        for (int q = 0; q < 4; ++q) { ldc0[q] = ldn0[q]; ldc1[q] = ldn1[q]; }
        __syncthreads();
    }
}

// =====================================================================
// Final head: FB=8 batches per block; class range split in 2.
// =====================================================================
__global__ void __launch_bounds__(256)
final_kernel(const float* __restrict__ Wout, const float* __restrict__ bout,
             float* __restrict__ out)
{
    const int bbase = blockIdx.x * FB;
    const int chalf = blockIdx.y;
    __shared__ float hs[FB][128];
    for (int i = threadIdx.x; i < FB * 128; i += 256)
        hs[i >> 7][i & 127] = g_h1last[bbase * 128 + i];
    __syncthreads();

    const int cbeg = chalf * 549;
    const int cend = cbeg + 549;
    for (int cl = cbeg + threadIdx.x; cl < cend; cl += 256) {
        const float4* wv = reinterpret_cast<const float4*>(Wout + (size_t)cl * 128);
        float a[FB];
#pragma unroll
        for (int b = 0; b < FB; ++b) a[b] = bout[cl];
#pragma unroll
        for (int k = 0; k < 32; ++k) {
            float4 v = wv[k];
#pragma unroll
            for (int b = 0; b < FB; ++b) {
                a[b] += hs[b][4 * k + 0] * v.x + hs[b][4 * k + 1] * v.y
                      + hs[b][4 * k + 2] * v.z + hs[b][4 * k + 3] * v.w;
            }
        }
#pragma unroll
        for (int b = 0; b < FB; ++b)
            out[(size_t)(bbase + b) * NCLS + cl] = a[b];
    }
}

// =====================================================================
extern "C" void kernel_launch(void* const* d_in, const int* in_sizes, int n_in,
                              void* d_out, int out_size)
{
    const float* x     = (const float*)d_in[0];
    const int*   lens  = (const int*)  d_in[1];
    const float* Wih0f = (const float*)d_in[2];
    const float* Whh0f = (const float*)d_in[3];
    const float* bih0f = (const float*)d_in[4];
    const float* bhh0f = (const float*)d_in[5];
    const float* Wih0b = (const float*)d_in[6];
    const float* Whh0b = (const float*)d_in[7];
    const float* bih0b = (const float*)d_in[8];
    const float* bhh0b = (const float*)d_in[9];
    const float* Wih1f = (const float*)d_in[10];
    const float* Whh1f = (const float*)d_in[11];
    const float* bih1f = (const float*)d_in[12];
    const float* bhh1f = (const float*)d_in[13];
    const float* Wih1b = (const float*)d_in[14];
    const float* Whh1b = (const float*)d_in[15];
    const float* bih1b = (const float*)d_in[16];
    const float* bhh1b = (const float*)d_in[17];
    const float* Wout  = (const float*)d_in[18];
    const float* bout  = (const float*)d_in[19];

    static bool attr_set = false;
    if (!attr_set) {
        cudaFuncSetAttribute(gates1_gemm_kernel,
                             cudaFuncAttributeMaxDynamicSharedMemorySize, GEMM_SMEM);
        attr_set = true;
    }

    lstm_l0_kernel<<<2 * (BQ / NB), 256>>>(x, lens,
                                           Wih0f, Whh0f, bih0f, bhh0f,
                                           Wih0b, Whh0b, bih0b, bhh0b);

    dim3 gg(TQ / GM_ROWS, BQ, 2);
    gates1_gemm_kernel<<<gg, 256, GEMM_SMEM>>>(lens, Wih1f, Wih1b,
                                               bih1f, bhh1f, bih1b, bhh1b);

    lstm_l1_kernel<<<2 * (BQ / NB), 256>>>(lens, Whh1f, Whh1b);

    dim3 gf(BQ / FB, 2);
    final_kernel<<<gf, 256>>>(Wout, bout, (float*)d_out);
}

// round 10
// speedup vs baseline: 1.0082x; 1.0082x over previous
#include <cuda_runtime.h>
#include <math.h>

#define BQ   512
#define TQ   1024
#define DQ   4
#define HQ   64
#define G4   256          // 4*H
#define NB   8            // batches per recurrent block (one block per SM)
#define NCLS 1098
#define FB   4            // batches per final-head block

#define HX_STRIDE 76      // [h(64) | x(4) | 1 | 0..]; conflict-free B-frag LDS

// ---------------- scratch (static device allocations only) ----------------
__device__ float g_g1[2][(size_t)BQ * TQ * G4];   // layer-1 gate preactivations per dir
__device__ float g_h0[(size_t)BQ * TQ * 128];     // layer-0 bidir output, [B][T][128]
__device__ float g_h1last[BQ * 128];              // gathered last timestep of layer 1

// ---------------- helpers ----------------
__device__ __forceinline__ float tanh_fast(float x) {
    float y; asm("tanh.approx.f32 %0,%1;" : "=f"(y) : "f"(x)); return y;
}
__device__ __forceinline__ float sig_fast(float x) {
    return fmaf(0.5f, tanh_fast(0.5f * x), 0.5f);
}
__device__ __forceinline__ unsigned tf32_rna(float v) {
    unsigned y; asm("cvt.rna.tf32.f32 %0,%1;" : "=r"(y) : "f"(v)); return y;
}
__device__ __forceinline__ void mma_tf32(float* c, const unsigned* a, unsigned b0, unsigned b1) {
    asm volatile(
        "mma.sync.aligned.m16n8k8.row.col.f32.tf32.tf32.f32 "
        "{%0,%1,%2,%3},{%4,%5,%6,%7},{%8,%9},{%0,%1,%2,%3};"
        : "+f"(c[0]), "+f"(c[1]), "+f"(c[2]), "+f"(c[3])
        : "r"(a[0]), "r"(a[1]), "r"(a[2]), "r"(a[3]), "r"(b0), "r"(b1));
}

// =====================================================================
// Layer 0: bidirectional LSTM; recurrent matvec on tensor cores with
// IN-THREAD pointwise phase (gate-remapped A fragments):
//   warp w, tile mt, tile-row j: gate = (mt*2 + (j>=8))*64 + 8w + (j&7)
// => thread (gid,tig) receives i,f (tile0) and g,o (tile1) of unit
//    u=8w+gid for batches 2tig, 2tig+1. c-state lives in registers.
// hx double-buffered => ONE __syncthreads per step.
// =====================================================================
__global__ void __launch_bounds__(256, 1)
lstm_l0_kernel(const float* __restrict__ x, const int* __restrict__ lens,
               const float* __restrict__ WihF, const float* __restrict__ WhhF,
               const float* __restrict__ bihF, const float* __restrict__ bhhF,
               const float* __restrict__ WihB, const float* __restrict__ WhhB,
               const float* __restrict__ bihB, const float* __restrict__ bhhB)
{
    const int dir   = blockIdx.x & 1;
    const int xb    = blockIdx.x >> 1;
    const int bbase = xb * NB;
    const int tid  = threadIdx.x;
    const int w    = tid >> 5;
    const int lane = tid & 31;
    const int gid  = lane >> 2;               // 0..7
    const int tig  = lane & 3;                // 0..3
    const int u    = w * 8 + gid;             // owned hidden unit
    const int b0   = 2 * tig, b1 = 2 * tig + 1;

    const float* Wih = dir ? WihB : WihF;
    const float* Whh = dir ? WhhB : WhhF;
    const float* bih = dir ? bihB : bihF;
    const float* bhh = dir ? bhhB : bhhF;

    // ---- A fragments, gate-remapped rows, K = 72 augmented
    unsigned afr[2][9][4];
#pragma unroll
    for (int mt = 0; mt < 2; ++mt) {
#pragma unroll
        for (int kc = 0; kc < 9; ++kc) {
#pragma unroll
            for (int e = 0; e < 4; ++e) {
                int g = (mt * 2 + (e & 1)) * 64 + u;   // i/f (mt0), g/o (mt1)
                int k = kc * 8 + tig + ((e & 2) ? 4 : 0);
                float v;
                if (k < 64)       v = Whh[g * HQ + k];
                else if (k < 68)  v = Wih[g * DQ + (k - 64)];
                else if (k == 68) v = bih[g] + bhh[g];
                else              v = 0.0f;
                afr[mt][kc][e] = tf32_rna(v);
            }
        }
    }

    __shared__ float hx[2][NB][HX_STRIDE];
    __shared__ int   lsh[NB];

    if (tid < NB) lsh[tid] = lens[bbase + tid];
    for (int i = tid; i < 2 * NB * HX_STRIDE; i += 256)
        (&hx[0][0][0])[i] = 0.0f;
    __syncthreads();
    if (tid < 2 * NB) hx[tid >> 3][tid & 7][68] = 1.0f;   // bias lane

    const int maxlen = lsh[0];                // lens sorted descending
    const int lenA = lsh[b0], lenB = lsh[b1];
    float c0 = 0.0f, c1 = 0.0f;

    if (tid < NB) {
        int len = lsh[tid];
        int tt  = dir ? (len - 1) : 0;
        float4 xv = reinterpret_cast<const float4*>(x)[(size_t)(bbase + tid) * TQ + tt];
        hx[0][tid][64] = xv.x; hx[0][tid][65] = xv.y;
        hx[0][tid][66] = xv.z; hx[0][tid][67] = xv.w;
    }
    __syncthreads();

    for (int t = 0; t < maxlen; ++t) {
        const int buf = t & 1, nbuf = buf ^ 1;

        // prefetch x(t+1) (overlaps MMA)
        float4 xn = make_float4(0.f, 0.f, 0.f, 0.f);
        if (tid < NB) {
            int tn  = (t + 1 < maxlen) ? (t + 1) : t;
            int len = lsh[tid];
            int tt  = dir ? ((tn < len) ? (len - 1 - tn) : tn) : tn;
            xn = reinterpret_cast<const float4*>(x)[(size_t)(bbase + tid) * TQ + tt];
        }

        // ---- phase A: tensor-core matvec, split accumulator chains
        const float* hxb = &hx[buf][gid][0];
        float a0[4] = {0.f, 0.f, 0.f, 0.f}, a1[4] = {0.f, 0.f, 0.f, 0.f};
        float e0[4] = {0.f, 0.f, 0.f, 0.f}, e1[4] = {0.f, 0.f, 0.f, 0.f};
#pragma unroll
        for (int kc = 0; kc < 9; kc += 2) {
            unsigned p = __float_as_uint(hxb[kc * 8 + tig]);
            unsigned q = __float_as_uint(hxb[kc * 8 + 4 + tig]);
            mma_tf32(a0, afr[0][kc], p, q);
            mma_tf32(a1, afr[1][kc], p, q);
        }
#pragma unroll
        for (int kc = 1; kc < 9; kc += 2) {
            unsigned p = __float_as_uint(hxb[kc * 8 + tig]);
            unsigned q = __float_as_uint(hxb[kc * 8 + 4 + tig]);
            mma_tf32(e0, afr[0][kc], p, q);
            mma_tf32(e1, afr[1][kc], p, q);
        }
#pragma unroll
        for (int e = 0; e < 4; ++e) { a0[e] += e0[e]; a1[e] += e1[e]; }

        // ---- phase B: in-thread (i=a0[0/1], f=a0[2/3], g=a1[0/1], o=a1[2/3])
        {
            float si = sig_fast(a0[0]);
            float sf = sig_fast(a0[2]);
            float tg = tanh_fast(a1[0]);
            float so = sig_fast(a1[2]);
            c0 = sf * c0 + si * tg;
            float h = so * tanh_fast(c0);
            hx[nbuf][b0][u] = h;
            int ts = dir ? ((t < lenA) ? (lenA - 1 - t) : t) : t;
            g_h0[((size_t)(bbase + b0) * TQ + ts) * 128 + dir * HQ + u] = h;
        }
        {
            float si = sig_fast(a0[1]);
            float sf = sig_fast(a0[3]);
            float tg = tanh_fast(a1[1]);
            float so = sig_fast(a1[3]);
            c1 = sf * c1 + si * tg;
            float h = so * tanh_fast(c1);
            hx[nbuf][b1][u] = h;
            int ts = dir ? ((t < lenB) ? (lenB - 1 - t) : t) : t;
            g_h0[((size_t)(bbase + b1) * TQ + ts) * 128 + dir * HQ + u] = h;
        }
        if (tid < NB) {
            hx[nbuf][tid][64] = xn.x; hx[nbuf][tid][65] = xn.y;
            hx[nbuf][tid][66] = xn.z; hx[nbuf][tid][67] = xn.w;
        }
        __syncthreads();
    }
}

// =====================================================================
// Layer-1 gate GEMM on tensor cores (R7, unchanged).
// =====================================================================
#define GM_ROWS   64
#define AS_STRIDE 132
#define WS_STRIDE 36
#define GEMM_SMEM ((64 * AS_STRIDE + 256 * WS_STRIDE) * 4)   // 70656 B

__global__ void __launch_bounds__(256, 2)
gates1_gemm_kernel(const int* __restrict__ lens,
                   const float* __restrict__ WihF, const float* __restrict__ WihB,
                   const float* __restrict__ bihF, const float* __restrict__ bhhF,
                   const float* __restrict__ bihB, const float* __restrict__ bhhB)
{
    const int tile  = blockIdx.x;
    const int b     = blockIdx.y;
    const int dir   = blockIdx.z;
    const int tbase = tile * GM_ROWS;

    const int len = lens[b];
    if (tbase >= len) return;

    extern __shared__ float sm[];
    float* As = sm;
    float* Ws = sm + 64 * AS_STRIDE;

    const int tid  = threadIdx.x;
    const int lane = tid & 31;
    const int w    = tid >> 5;
    const int wr   = w & 3;
    const int wc   = w >> 2;
    const int gid  = lane >> 2;
    const int tig  = lane & 3;

    const float* Wih = dir ? WihB : WihF;
    const float* bih = dir ? bihB : bihF;
    const float* bhh = dir ? bhhB : bhhF;

    float acc[16][4];
#pragma unroll
    for (int nt = 0; nt < 16; ++nt) {
        int col0 = wc * 128 + nt * 8 + 2 * tig;
        float bv0 = bih[col0]     + bhh[col0];
        float bv1 = bih[col0 + 1] + bhh[col0 + 1];
        acc[nt][0] = bv0; acc[nt][1] = bv1;
        acc[nt][2] = bv0; acc[nt][3] = bv1;
    }

    const float* h0b = g_h0 + (size_t)b * TQ * 128;
#pragma unroll
    for (int i = 0; i < 8; ++i) {
        int idx = tid + 256 * i;
        int r   = idx >> 5, kq = idx & 31;
        int srow = tbase + r;
        if (dir) srow = (srow < len) ? (len - 1 - srow) : srow;
        float4 v = *reinterpret_cast<const float4*>(h0b + (size_t)srow * 128 + 4 * kq);
        *reinterpret_cast<float4*>(&As[r * AS_STRIDE + 4 * kq]) = v;
    }

    const int r0 = wr * 16 + gid;

    for (int k0 = 0; k0 < 128; k0 += 32) {
        __syncthreads();
#pragma unroll
        for (int i = 0; i < 8; ++i) {
            int idx = tid + 256 * i;
            int n   = idx >> 3, kq = idx & 7;
            float4 v = *reinterpret_cast<const float4*>(Wih + (size_t)n * 128 + k0 + 4 * kq);
            *reinterpret_cast<float4*>(&Ws[n * WS_STRIDE + 4 * kq]) = v;
        }
        __syncthreads();

#pragma unroll
        for (int ks = 0; ks < 4; ++ks) {
            const int kl = ks * 8;
            unsigned a[4];
            a[0] = __float_as_uint(As[r0 * AS_STRIDE + k0 + kl + tig]);
            a[1] = __float_as_uint(As[(r0 + 8) * AS_STRIDE + k0 + kl + tig]);
            a[2] = __float_as_uint(As[r0 * AS_STRIDE + k0 + kl + 4 + tig]);
            a[3] = __float_as_uint(As[(r0 + 8) * AS_STRIDE + k0 + kl + 4 + tig]);
#pragma unroll
            for (int nt = 0; nt < 16; ++nt) {
                int n = wc * 128 + nt * 8 + gid;
                unsigned b0 = __float_as_uint(Ws[n * WS_STRIDE + kl + tig]);
                unsigned b1 = __float_as_uint(Ws[n * WS_STRIDE + kl + 4 + tig]);
                mma_tf32(acc[nt], a, b0, b1);
            }
        }
    }

    float* outp = g_g1[dir] + ((size_t)b * TQ + tbase) * G4;
#pragma unroll
    for (int nt = 0; nt < 16; ++nt) {
        int col0 = wc * 128 + nt * 8 + 2 * tig;
        *reinterpret_cast<float2*>(outp + (size_t)r0 * G4 + col0) =
            make_float2(acc[nt][0], acc[nt][1]);
        *reinterpret_cast<float2*>(outp + (size_t)(r0 + 8) * G4 + col0) =
            make_float2(acc[nt][2], acc[nt][3]);
    }
}

// =====================================================================
// Layer 1: recurrent over precomputed gates, in-thread pointwise.
// Precomputed preactivations are folded into the MMA accumulator init
// (prefetched one step ahead). One __syncthreads per step.
// =====================================================================
__global__ void __launch_bounds__(256, 1)
lstm_l1_kernel(const int* __restrict__ lens,
               const float* __restrict__ WhhF, const float* __restrict__ WhhB)
{
    const int dir   = blockIdx.x & 1;
    const int xb    = blockIdx.x >> 1;
    const int bbase = xb * NB;
    const int tid  = threadIdx.x;
    const int w    = tid >> 5;
    const int lane = tid & 31;
    const int gid  = lane >> 2;
    const int tig  = lane & 3;
    const int u    = w * 8 + gid;
    const int b0   = 2 * tig, b1 = 2 * tig + 1;

    const float* Whh = dir ? WhhB : WhhF;
    const float* gin = g_g1[dir];

    // ---- A fragments, gate-remapped rows, K = 64
    unsigned afr[2][8][4];
#pragma unroll
    for (int mt = 0; mt < 2; ++mt) {
#pragma unroll
        for (int kc = 0; kc < 8; ++kc) {
#pragma unroll
            for (int e = 0; e < 4; ++e) {
                int g = (mt * 2 + (e & 1)) * 64 + u;
                int k = kc * 8 + tig + ((e & 2) ? 4 : 0);
                afr[mt][kc][e] = tf32_rna(Whh[g * HQ + k]);
            }
        }
    }

    __shared__ float hx[2][NB][HX_STRIDE];
    __shared__ int   lsh[NB];

    if (tid < NB) lsh[tid] = lens[bbase + tid];
    for (int i = tid; i < 2 * NB * HX_STRIDE; i += 256)
        (&hx[0][0][0])[i] = 0.0f;
    __syncthreads();

    const int maxlen = lsh[0];
    const int lenA = lsh[b0], lenB = lsh[b1];
    float c0 = 0.0f, c1 = 0.0f;

    // preact base offsets: pre[type][batch] at [ (bbase+b)*TQ + t ]*G4 + type*64 + u
    const float* pbase0 = gin + (size_t)(bbase + b0) * TQ * G4 + u;
    const float* pbase1 = gin + (size_t)(bbase + b1) * TQ * G4 + u;

    float ldc[8];   // [type*2 + (0:b0,1:b1)]
#pragma unroll
    for (int ty = 0; ty < 4; ++ty) {
        ldc[ty * 2 + 0] = pbase0[ty * 64];
        ldc[ty * 2 + 1] = pbase1[ty * 64];
    }

    for (int t = 0; t < maxlen; ++t) {
        const int buf = t & 1, nbuf = buf ^ 1;

        // prefetch next-step preacts (overlaps MMA)
        float ldn[8];
        const int tn = (t + 1 < maxlen) ? (t + 1) : t;
#pragma unroll
        for (int ty = 0; ty < 4; ++ty) {
            ldn[ty * 2 + 0] = pbase0[(size_t)tn * G4 + ty * 64];
            ldn[ty * 2 + 1] = pbase1[(size_t)tn * G4 + ty * 64];
        }

        // ---- phase A: MMA with preacts folded into accumulator init
        const float* hxb = &hx[buf][gid][0];
        float a0[4] = { ldc[0], ldc[1], ldc[2], ldc[3] };   // i(b0,b1), f(b0,b1)
        float a1[4] = { ldc[4], ldc[5], ldc[6], ldc[7] };   // g(b0,b1), o(b0,b1)
        float e0[4] = {0.f, 0.f, 0.f, 0.f}, e1[4] = {0.f, 0.f, 0.f, 0.f};
#pragma unroll
        for (int kc = 0; kc < 8; kc += 2) {
            unsigned p = __float_as_uint(hxb[kc * 8 + tig]);
            unsigned q = __float_as_uint(hxb[kc * 8 + 4 + tig]);
            mma_tf32(a0, afr[0][kc], p, q);
            mma_tf32(a1, afr[1][kc], p, q);
        }
#pragma unroll
        for (int kc = 1; kc < 8; kc += 2) {
            unsigned p = __float_as_uint(hxb[kc * 8 + tig]);
            unsigned q = __float_as_uint(hxb[kc * 8 + 4 + tig]);
            mma_tf32(e0, afr[0][kc], p, q);
            mma_tf32(e1, afr[1][kc], p, q);
        }
#pragma unroll
        for (int e = 0; e < 4; ++e) { a0[e] += e0[e]; a1[e] += e1[e]; }

        // ---- phase B: in-thread
        {
            float si = sig_fast(a0[0]);
            float sf = sig_fast(a0[2]);
            float tg = tanh_fast(a1[0]);
            float so = sig_fast(a1[2]);
            c0 = sf * c0 + si * tg;
            float h = so * tanh_fast(c0);
            hx[nbuf][b0][u] = h;
            if (dir ? (t == 0) : (t == lenA - 1))
                g_h1last[(bbase + b0) * 128 + dir * HQ + u] = h;
        }
        {
            float si = sig_fast(a0[1]);
            float sf = sig_fast(a0[3]);
            float tg = tanh_fast(a1[1]);
            float so = sig_fast(a1[3]);
            c1 = sf * c1 + si * tg;
            float h = so * tanh_fast(c1);
            hx[nbuf][b1][u] = h;
            if (dir ? (t == 0) : (t == lenB - 1))
                g_h1last[(bbase + b1) * 128 + dir * HQ + u] = h;
        }
#pragma unroll
        for (int q = 0; q < 8; ++q) ldc[q] = ldn[q];
        __syncthreads();
    }
}

// =====================================================================
// Final head: FB=4 batches per block; class range split in 2.
// =====================================================================
__global__ void __launch_bounds__(256)
final_kernel(const float* __restrict__ Wout, const float* __restrict__ bout,
             float* __restrict__ out)
{
    const int bbase = blockIdx.x * FB;
    const int chalf = blockIdx.y;
    __shared__ float hs[FB][128];
    for (int i = threadIdx.x; i < FB * 128; i += 256)
        hs[i >> 7][i & 127] = g_h1last[bbase * 128 + i];
    __syncthreads();

    const int cbeg = chalf * 549;
    const int cend = cbeg + 549;
    for (int cl = cbeg + threadIdx.x; cl < cend; cl += 256) {
        const float4* wv = reinterpret_cast<const float4*>(Wout + (size_t)cl * 128);
        float a[FB];
#pragma unroll
        for (int b = 0; b < FB; ++b) a[b] = bout[cl];
#pragma unroll
        for (int k = 0; k < 32; ++k) {
            float4 v = wv[k];
#pragma unroll
            for (int b = 0; b < FB; ++b) {
                a[b] += hs[b][4 * k + 0] * v.x + hs[b][4 * k + 1] * v.y
                      + hs[b][4 * k + 2] * v.z + hs[b][4 * k + 3] * v.w;
            }
        }
#pragma unroll
        for (int b = 0; b < FB; ++b)
            out[(size_t)(bbase + b) * NCLS + cl] = a[b];
    }
}

// =====================================================================
extern "C" void kernel_launch(void* const* d_in, const int* in_sizes, int n_in,
                              void* d_out, int out_size)
{
    const float* x     = (const float*)d_in[0];
    const int*   lens  = (const int*)  d_in[1];
    const float* Wih0f = (const float*)d_in[2];
    const float* Whh0f = (const float*)d_in[3];
    const float* bih0f = (const float*)d_in[4];
    const float* bhh0f = (const float*)d_in[5];
    const float* Wih0b = (const float*)d_in[6];
    const float* Whh0b = (const float*)d_in[7];
    const float* bih0b = (const float*)d_in[8];
    const float* bhh0b = (const float*)d_in[9];
    const float* Wih1f = (const float*)d_in[10];
    const float* Whh1f = (const float*)d_in[11];
    const float* bih1f = (const float*)d_in[12];
    const float* bhh1f = (const float*)d_in[13];
    const float* Wih1b = (const float*)d_in[14];
    const float* Whh1b = (const float*)d_in[15];
    const float* bih1b = (const float*)d_in[16];
    const float* bhh1b = (const float*)d_in[17];
    const float* Wout  = (const float*)d_in[18];
    const float* bout  = (const float*)d_in[19];

    static bool attr_set = false;
    if (!attr_set) {
        cudaFuncSetAttribute(gates1_gemm_kernel,
                             cudaFuncAttributeMaxDynamicSharedMemorySize, GEMM_SMEM);
        attr_set = true;
    }

    lstm_l0_kernel<<<2 * (BQ / NB), 256>>>(x, lens,
                                           Wih0f, Whh0f, bih0f, bhh0f,
                                           Wih0b, Whh0b, bih0b, bhh0b);

    dim3 gg(TQ / GM_ROWS, BQ, 2);
    gates1_gemm_kernel<<<gg, 256, GEMM_SMEM>>>(lens, Wih1f, Wih1b,
                                               bih1f, bhh1f, bih1b, bhh1b);

    lstm_l1_kernel<<<2 * (BQ / NB), 256>>>(lens, Whh1f, Whh1b);

    dim3 gf(BQ / FB, 2);
    final_kernel<<<gf, 256>>>(Wout, bout, (float*)d_out);
}

// round 11
// speedup vs baseline: 1.0473x; 1.0388x over previous
#include <cuda_runtime.h>
#include <cuda_fp16.h>
#include <math.h>

#define BQ   512
#define TQ   1024
#define DQ   4
#define HQ   64
#define G4   256          // 4*H
#define NB   4            // batches per recurrent block (2 blocks/SM, paired)
#define NCLS 1098
#define FB   4            // batches per final-head block

#define HXH_STRIDE 88     // halves; conflict-free for B-frag LDS pattern

// ---------------- scratch (static device allocations only) ----------------
__device__ float g_g1[2][(size_t)BQ * TQ * G4];   // layer-1 gate preactivations per dir
__device__ float g_h0[(size_t)BQ * TQ * 128];     // layer-0 bidir output, [B][T][128]
__device__ float g_h1last[BQ * 128];              // gathered last timestep of layer 1

// ---------------- helpers ----------------
__device__ __forceinline__ float tanh_fast(float x) {
    float y; asm("tanh.approx.f32 %0,%1;" : "=f"(y) : "f"(x)); return y;
}
__device__ __forceinline__ float sig_fast(float x) {
    return fmaf(0.5f, tanh_fast(0.5f * x), 0.5f);
}
__device__ __forceinline__ unsigned pack_h2(float lo, float hi) {
    __half2 h = __floats2half2_rn(lo, hi);
    return *reinterpret_cast<unsigned*>(&h);
}
// fp16 MMA, fp32 accumulate
__device__ __forceinline__ void mma_f16(float* c, const unsigned* a, unsigned b0, unsigned b1) {
    asm volatile(
        "mma.sync.aligned.m16n8k16.row.col.f32.f16.f16.f32 "
        "{%0,%1,%2,%3},{%4,%5,%6,%7},{%8,%9},{%0,%1,%2,%3};"
        : "+f"(c[0]), "+f"(c[1]), "+f"(c[2]), "+f"(c[3])
        : "r"(a[0]), "r"(a[1]), "r"(a[2]), "r"(a[3]), "r"(b0), "r"(b1));
}
// tf32 MMA (for the big GEMM)
__device__ __forceinline__ void mma_tf32(float* c, const unsigned* a, unsigned b0, unsigned b1) {
    asm volatile(
        "mma.sync.aligned.m16n8k8.row.col.f32.tf32.tf32.f32 "
        "{%0,%1,%2,%3},{%4,%5,%6,%7},{%8,%9},{%0,%1,%2,%3};"
        : "+f"(c[0]), "+f"(c[1]), "+f"(c[2]), "+f"(c[3])
        : "r"(a[0]), "r"(a[1]), "r"(a[2]), "r"(a[3]), "r"(b0), "r"(b1));
}

// block (0..255) -> sorted group id: pairs wave-1 co-resident blocks
// (bid, bid+148) with (long, short) sequence groups.
__device__ __forceinline__ void block_to_group(int bid, int& dir, int& xb) {
    int j = (bid < 148) ? bid : (403 - bid);
    dir = j & 1;
    xb  = j >> 1;
}

// =====================================================================
// Layer 0: bidirectional LSTM; recurrent matvec on fp16 tensor cores,
// in-thread pointwise (gate-remapped A rows):
//   A reg e: gate = (mt*2 + (e&1))*64 + u,  k = kc*16 + 2tig + (e&2?8:0)
// Thread (gid,tig) gets i,f (mt0) & g,o (mt1) of unit u=8w+gid for
// MMA columns b0=2tig, b1=2tig+1 (real iff tig<2 at NB=4).
// hx (fp16) double-buffered => ONE __syncthreads per step.
// K augmented to 80: [h(64) | x(4) | 1 | pad(11)]
// =====================================================================
__global__ void __launch_bounds__(256, 2)
lstm_l0_kernel(const float* __restrict__ x, const int* __restrict__ lens,
               const float* __restrict__ WihF, const float* __restrict__ WhhF,
               const float* __restrict__ bihF, const float* __restrict__ bhhF,
               const float* __restrict__ WihB, const float* __restrict__ WhhB,
               const float* __restrict__ bihB, const float* __restrict__ bhhB)
{
    int dir, xb;
    block_to_group(blockIdx.x, dir, xb);
    const int bbase = xb * NB;
    const int tid  = threadIdx.x;
    const int w    = tid >> 5;
    const int lane = tid & 31;
    const int gid  = lane >> 2;               // 0..7 (MMA row grp / B column)
    const int tig  = lane & 3;                // 0..3
    const int u    = w * 8 + gid;             // owned hidden unit
    const int b0   = 2 * tig, b1 = 2 * tig + 1;
    const bool real = (tig < 2);              // columns 0..3 are real batches

    const float* Wih = dir ? WihB : WihF;
    const float* Whh = dir ? WhhB : WhhF;
    const float* bih = dir ? bihB : bihF;
    const float* bhh = dir ? bhhB : bhhF;

    // ---- A fragments (fp16), gate-remapped rows, K = 80 augmented
    unsigned afr[2][5][4];
#pragma unroll
    for (int mt = 0; mt < 2; ++mt) {
#pragma unroll
        for (int kc = 0; kc < 5; ++kc) {
#pragma unroll
            for (int e = 0; e < 4; ++e) {
                int g  = (mt * 2 + (e & 1)) * 64 + u;
                int kb = kc * 16 + 2 * tig + ((e & 2) ? 8 : 0);
                float v0, v1;
                {
                    int k = kb;
                    v0 = (k < 64) ? Whh[g * HQ + k]
                       : (k < 68) ? Wih[g * DQ + (k - 64)]
                       : (k == 68) ? (bih[g] + bhh[g]) : 0.0f;
                }
                {
                    int k = kb + 1;
                    v1 = (k < 64) ? Whh[g * HQ + k]
                       : (k < 68) ? Wih[g * DQ + (k - 64)]
                       : (k == 68) ? (bih[g] + bhh[g]) : 0.0f;
                }
                afr[mt][kc][e] = pack_h2(v0, v1);
            }
        }
    }

    __shared__ __half hx[2][8][HXH_STRIDE];
    __shared__ int    lsh[8];

    if (tid < 8) lsh[tid] = lens[bbase + (tid < NB ? tid : NB - 1)];
    for (int i = tid; i < 2 * 8 * HXH_STRIDE; i += 256)
        (&hx[0][0][0])[i] = __float2half(0.0f);
    __syncthreads();
    if (tid < 16) hx[tid >> 3][tid & 7][68] = __float2half(1.0f);  // bias lane

    const int maxlen = lsh[0];                // lens sorted descending
    const int lenA = lsh[b0], lenB = lsh[b1];
    float c0 = 0.0f, c1 = 0.0f;

    if (tid < NB) {
        int len = lsh[tid];
        int tt  = dir ? (len - 1) : 0;
        float4 xv = reinterpret_cast<const float4*>(x)[(size_t)(bbase + tid) * TQ + tt];
        hx[0][tid][64] = __float2half(xv.x); hx[0][tid][65] = __float2half(xv.y);
        hx[0][tid][66] = __float2half(xv.z); hx[0][tid][67] = __float2half(xv.w);
    }
    __syncthreads();

    for (int t = 0; t < maxlen; ++t) {
        const int buf = t & 1, nbuf = buf ^ 1;

        // prefetch x(t+1) (overlaps MMA)
        float4 xn = make_float4(0.f, 0.f, 0.f, 0.f);
        if (tid < NB) {
            int tn  = (t + 1 < maxlen) ? (t + 1) : t;
            int len = lsh[tid];
            int tt  = dir ? ((tn < len) ? (len - 1 - tn) : tn) : tn;
            xn = reinterpret_cast<const float4*>(x)[(size_t)(bbase + tid) * TQ + tt];
        }

        // ---- phase A: fp16 tensor-core matvec, split accumulator chains
        const __half* hxb = &hx[buf][gid][0];
        float a0[4] = {0.f, 0.f, 0.f, 0.f}, a1[4] = {0.f, 0.f, 0.f, 0.f};
        float e0[4] = {0.f, 0.f, 0.f, 0.f}, e1[4] = {0.f, 0.f, 0.f, 0.f};
#pragma unroll
        for (int kc = 0; kc < 5; kc += 2) {
            unsigned p = *reinterpret_cast<const unsigned*>(&hxb[kc * 16 + 2 * tig]);
            unsigned q = *reinterpret_cast<const unsigned*>(&hxb[kc * 16 + 2 * tig + 8]);
            mma_f16(a0, afr[0][kc], p, q);
            mma_f16(a1, afr[1][kc], p, q);
        }
#pragma unroll
        for (int kc = 1; kc < 5; kc += 2) {
            unsigned p = *reinterpret_cast<const unsigned*>(&hxb[kc * 16 + 2 * tig]);
            unsigned q = *reinterpret_cast<const unsigned*>(&hxb[kc * 16 + 2 * tig + 8]);
            mma_f16(e0, afr[0][kc], p, q);
            mma_f16(e1, afr[1][kc], p, q);
        }
#pragma unroll
        for (int e = 0; e < 4; ++e) { a0[e] += e0[e]; a1[e] += e1[e]; }

        // ---- phase B: in-thread (i=a0[0/1], f=a0[2/3], g=a1[0/1], o=a1[2/3])
        {
            float si = sig_fast(a0[0]);
            float sf = sig_fast(a0[2]);
            float tg = tanh_fast(a1[0]);
            float so = sig_fast(a1[2]);
            c0 = sf * c0 + si * tg;
            float h = so * tanh_fast(c0);
            if (real) {
                hx[nbuf][b0][u] = __float2half_rn(h);
                int ts = dir ? ((t < lenA) ? (lenA - 1 - t) : t) : t;
                g_h0[((size_t)(bbase + b0) * TQ + ts) * 128 + dir * HQ + u] = h;
            }
        }
        {
            float si = sig_fast(a0[1]);
            float sf = sig_fast(a0[3]);
            float tg = tanh_fast(a1[1]);
            float so = sig_fast(a1[3]);
            c1 = sf * c1 + si * tg;
            float h = so * tanh_fast(c1);
            if (real) {
                hx[nbuf][b1][u] = __float2half_rn(h);
                int ts = dir ? ((t < lenB) ? (lenB - 1 - t) : t) : t;
                g_h0[((size_t)(bbase + b1) * TQ + ts) * 128 + dir * HQ + u] = h;
            }
        }
        if (tid < NB) {
            hx[nbuf][tid][64] = __float2half(xn.x);
            hx[nbuf][tid][65] = __float2half(xn.y);
            hx[nbuf][tid][66] = __float2half(xn.z);
            hx[nbuf][tid][67] = __float2half(xn.w);
        }
        __syncthreads();
    }
}

// =====================================================================
// Layer-1 gate GEMM on tensor cores (R7 tf32, unchanged).
// =====================================================================
#define GM_ROWS   64
#define AS_STRIDE 132
#define WS_STRIDE 36
#define GEMM_SMEM ((64 * AS_STRIDE + 256 * WS_STRIDE) * 4)   // 70656 B

__global__ void __launch_bounds__(256, 2)
gates1_gemm_kernel(const int* __restrict__ lens,
                   const float* __restrict__ WihF, const float* __restrict__ WihB,
                   const float* __restrict__ bihF, const float* __restrict__ bhhF,
                   const float* __restrict__ bihB, const float* __restrict__ bhhB)
{
    const int tile  = blockIdx.x;
    const int b     = blockIdx.y;
    const int dir   = blockIdx.z;
    const int tbase = tile * GM_ROWS;

    const int len = lens[b];
    if (tbase >= len) return;

    extern __shared__ float sm[];
    float* As = sm;
    float* Ws = sm + 64 * AS_STRIDE;

    const int tid  = threadIdx.x;
    const int lane = tid & 31;
    const int w    = tid >> 5;
    const int wr   = w & 3;
    const int wc   = w >> 2;
    const int gid  = lane >> 2;
    const int tig  = lane & 3;

    const float* Wih = dir ? WihB : WihF;
    const float* bih = dir ? bihB : bihF;
    const float* bhh = dir ? bhhB : bhhF;

    float acc[16][4];
#pragma unroll
    for (int nt = 0; nt < 16; ++nt) {
        int col0 = wc * 128 + nt * 8 + 2 * tig;
        float bv0 = bih[col0]     + bhh[col0];
        float bv1 = bih[col0 + 1] + bhh[col0 + 1];
        acc[nt][0] = bv0; acc[nt][1] = bv1;
        acc[nt][2] = bv0; acc[nt][3] = bv1;
    }

    const float* h0b = g_h0 + (size_t)b * TQ * 128;
#pragma unroll
    for (int i = 0; i < 8; ++i) {
        int idx = tid + 256 * i;
        int r   = idx >> 5, kq = idx & 31;
        int srow = tbase + r;
        if (dir) srow = (srow < len) ? (len - 1 - srow) : srow;
        float4 v = *reinterpret_cast<const float4*>(h0b + (size_t)srow * 128 + 4 * kq);
        *reinterpret_cast<float4*>(&As[r * AS_STRIDE + 4 * kq]) = v;
    }

    const int r0 = wr * 16 + gid;

    for (int k0 = 0; k0 < 128; k0 += 32) {
        __syncthreads();
#pragma unroll
        for (int i = 0; i < 8; ++i) {
            int idx = tid + 256 * i;
            int n   = idx >> 3, kq = idx & 7;
            float4 v = *reinterpret_cast<const float4*>(Wih + (size_t)n * 128 + k0 + 4 * kq);
            *reinterpret_cast<float4*>(&Ws[n * WS_STRIDE + 4 * kq]) = v;
        }
        __syncthreads();

#pragma unroll
        for (int ks = 0; ks < 4; ++ks) {
            const int kl = ks * 8;
            unsigned a[4];
            a[0] = __float_as_uint(As[r0 * AS_STRIDE + k0 + kl + tig]);
            a[1] = __float_as_uint(As[(r0 + 8) * AS_STRIDE + k0 + kl + tig]);
            a[2] = __float_as_uint(As[r0 * AS_STRIDE + k0 + kl + 4 + tig]);
            a[3] = __float_as_uint(As[(r0 + 8) * AS_STRIDE + k0 + kl + 4 + tig]);
#pragma unroll
            for (int nt = 0; nt < 16; ++nt) {
                int n = wc * 128 + nt * 8 + gid;
                unsigned b0 = __float_as_uint(Ws[n * WS_STRIDE + kl + tig]);
                unsigned b1 = __float_as_uint(Ws[n * WS_STRIDE + kl + 4 + tig]);
                mma_tf32(acc[nt], a, b0, b1);
            }
        }
    }

    float* outp = g_g1[dir] + ((size_t)b * TQ + tbase) * G4;
#pragma unroll
    for (int nt = 0; nt < 16; ++nt) {
        int col0 = wc * 128 + nt * 8 + 2 * tig;
        *reinterpret_cast<float2*>(outp + (size_t)r0 * G4 + col0) =
            make_float2(acc[nt][0], acc[nt][1]);
        *reinterpret_cast<float2*>(outp + (size_t)(r0 + 8) * G4 + col0) =
            make_float2(acc[nt][2], acc[nt][3]);
    }
}

// =====================================================================
// Layer 1: recurrent over precomputed gates; fp16 MMA, in-thread
// pointwise, preacts folded into accumulator init. K = 64 (4 chunks).
// =====================================================================
__global__ void __launch_bounds__(256, 2)
lstm_l1_kernel(const int* __restrict__ lens,
               const float* __restrict__ WhhF, const float* __restrict__ WhhB)
{
    int dir, xb;
    block_to_group(blockIdx.x, dir, xb);
    const int bbase = xb * NB;
    const int tid  = threadIdx.x;
    const int w    = tid >> 5;
    const int lane = tid & 31;
    const int gid  = lane >> 2;
    const int tig  = lane & 3;
    const int u    = w * 8 + gid;
    const int b0   = 2 * tig, b1 = 2 * tig + 1;
    const bool real = (tig < 2);

    const float* Whh = dir ? WhhB : WhhF;
    const float* gin = g_g1[dir];

    // ---- A fragments (fp16), gate-remapped rows, K = 64
    unsigned afr[2][4][4];
#pragma unroll
    for (int mt = 0; mt < 2; ++mt) {
#pragma unroll
        for (int kc = 0; kc < 4; ++kc) {
#pragma unroll
            for (int e = 0; e < 4; ++e) {
                int g  = (mt * 2 + (e & 1)) * 64 + u;
                int kb = kc * 16 + 2 * tig + ((e & 2) ? 8 : 0);
                afr[mt][kc][e] = pack_h2(Whh[g * HQ + kb], Whh[g * HQ + kb + 1]);
            }
        }
    }

    __shared__ __half hx[2][8][HXH_STRIDE];
    __shared__ int    lsh[8];

    if (tid < 8) lsh[tid] = lens[bbase + (tid < NB ? tid : NB - 1)];
    for (int i = tid; i < 2 * 8 * HXH_STRIDE; i += 256)
        (&hx[0][0][0])[i] = __float2half(0.0f);
    __syncthreads();

    const int maxlen = lsh[0];
    const int lenA = lsh[b0], lenB = lsh[b1];
    float c0 = 0.0f, c1 = 0.0f;

    // preact streams for real columns (dummy lanes read batch 0 harmlessly)
    const int rb0 = real ? b0 : 0, rb1 = real ? b1 : 0;
    const float* pbase0 = gin + (size_t)(bbase + rb0) * TQ * G4 + u;
    const float* pbase1 = gin + (size_t)(bbase + rb1) * TQ * G4 + u;

    float ldc[8];
#pragma unroll
    for (int ty = 0; ty < 4; ++ty) {
        ldc[ty * 2 + 0] = pbase0[ty * 64];
        ldc[ty * 2 + 1] = pbase1[ty * 64];
    }

    for (int t = 0; t < maxlen; ++t) {
        const int buf = t & 1, nbuf = buf ^ 1;

        // prefetch next-step preacts (overlaps MMA)
        float ldn[8];
        const int tn = (t + 1 < maxlen) ? (t + 1) : t;
#pragma unroll
        for (int ty = 0; ty < 4; ++ty) {
            ldn[ty * 2 + 0] = pbase0[(size_t)tn * G4 + ty * 64];
            ldn[ty * 2 + 1] = pbase1[(size_t)tn * G4 + ty * 64];
        }

        // ---- phase A: fp16 MMA, preacts folded into accumulator init
        const __half* hxb = &hx[buf][gid][0];
        float a0[4] = { ldc[0], ldc[1], ldc[2], ldc[3] };   // i(b0,b1), f(b0,b1)
        float a1[4] = { ldc[4], ldc[5], ldc[6], ldc[7] };   // g(b0,b1), o(b0,b1)
        float e0[4] = {0.f, 0.f, 0.f, 0.f}, e1[4] = {0.f, 0.f, 0.f, 0.f};
#pragma unroll
        for (int kc = 0; kc < 4; kc += 2) {
            unsigned p = *reinterpret_cast<const unsigned*>(&hxb[kc * 16 + 2 * tig]);
            unsigned q = *reinterpret_cast<const unsigned*>(&hxb[kc * 16 + 2 * tig + 8]);
            mma_f16(a0, afr[0][kc], p, q);
            mma_f16(a1, afr[1][kc], p, q);
        }
#pragma unroll
        for (int kc = 1; kc < 4; kc += 2) {
            unsigned p = *reinterpret_cast<const unsigned*>(&hxb[kc * 16 + 2 * tig]);
            unsigned q = *reinterpret_cast<const unsigned*>(&hxb[kc * 16 + 2 * tig + 8]);
            mma_f16(e0, afr[1][kc], p, q);   // note: e-chains per tile below
            mma_f16(e1, afr[0][kc], p, q);
        }
        // merge (e1 belongs to tile0, e0 to tile1)
#pragma unroll
        for (int e = 0; e < 4; ++e) { a0[e] += e1[e]; a1[e] += e0[e]; }

        // ---- phase B: in-thread
        {
            float si = sig_fast(a0[0]);
            float sf = sig_fast(a0[2]);
            float tg = tanh_fast(a1[0]);
            float so = sig_fast(a1[2]);
            c0 = sf * c0 + si * tg;
            float h = so * tanh_fast(c0);
            if (real) {
                hx[nbuf][b0][u] = __float2half_rn(h);
                if (dir ? (t == 0) : (t == lenA - 1))
                    g_h1last[(bbase + b0) * 128 + dir * HQ + u] = h;
            }
        }
        {
            float si = sig_fast(a0[1]);
            float sf = sig_fast(a0[3]);
            float tg = tanh_fast(a1[1]);
            float so = sig_fast(a1[3]);
            c1 = sf * c1 + si * tg;
            float h = so * tanh_fast(c1);
            if (real) {
                hx[nbuf][b1][u] = __float2half_rn(h);
                if (dir ? (t == 0) : (t == lenB - 1))
                    g_h1last[(bbase + b1) * 128 + dir * HQ + u] = h;
            }
        }
#pragma unroll
        for (int q = 0; q < 8; ++q) ldc[q] = ldn[q];
        __syncthreads();
    }
}

// =====================================================================
// Final head: FB=4 batches per block; class range split in 2.
// =====================================================================
__global__ void __launch_bounds__(256)
final_kernel(const float* __restrict__ Wout, const float* __restrict__ bout,
             float* __restrict__ out)
{
    const int bbase = blockIdx.x * FB;
    const int chalf = blockIdx.y;
    __shared__ float hs[FB][128];
    for (int i = threadIdx.x; i < FB * 128; i += 256)
        hs[i >> 7][i & 127] = g_h1last[bbase * 128 + i];
    __syncthreads();

    const int cbeg = chalf * 549;
    const int cend = cbeg + 549;
    for (int cl = cbeg + threadIdx.x; cl < cend; cl += 256) {
        const float4* wv = reinterpret_cast<const float4*>(Wout + (size_t)cl * 128);
        float a[FB];
#pragma unroll
        for (int b = 0; b < FB; ++b) a[b] = bout[cl];
#pragma unroll
        for (int k = 0; k < 32; ++k) {
            float4 v = wv[k];
#pragma unroll
            for (int b = 0; b < FB; ++b) {
                a[b] += hs[b][4 * k + 0] * v.x + hs[b][4 * k + 1] * v.y
                      + hs[b][4 * k + 2] * v.z + hs[b][4 * k + 3] * v.w;
            }
        }
#pragma unroll
        for (int b = 0; b < FB; ++b)
            out[(size_t)(bbase + b) * NCLS + cl] = a[b];
    }
}

// =====================================================================
extern "C" void kernel_launch(void* const* d_in, const int* in_sizes, int n_in,
                              void* d_out, int out_size)
{
    const float* x     = (const float*)d_in[0];
    const int*   lens  = (const int*)  d_in[1];
    const float* Wih0f = (const float*)d_in[2];
    const float* Whh0f = (const float*)d_in[3];
    const float* bih0f = (const float*)d_in[4];
    const float* bhh0f = (const float*)d_in[5];
    const float* Wih0b = (const float*)d_in[6];
    const float* Whh0b = (const float*)d_in[7];
    const float* bih0b = (const float*)d_in[8];
    const float* bhh0b = (const float*)d_in[9];
    const float* Wih1f = (const float*)d_in[10];
    const float* Whh1f = (const float*)d_in[11];
    const float* bih1f = (const float*)d_in[12];
    const float* bhh1f = (const float*)d_in[13];
    const float* Wih1b = (const float*)d_in[14];
    const float* Whh1b = (const float*)d_in[15];
    const float* bih1b = (const float*)d_in[16];
    const float* bhh1b = (const float*)d_in[17];
    const float* Wout  = (const float*)d_in[18];
    const float* bout  = (const float*)d_in[19];

    static bool attr_set = false;
    if (!attr_set) {
        cudaFuncSetAttribute(gates1_gemm_kernel,
                             cudaFuncAttributeMaxDynamicSharedMemorySize, GEMM_SMEM);
        attr_set = true;
    }

    lstm_l0_kernel<<<256, 256>>>(x, lens,
                                 Wih0f, Whh0f, bih0f, bhh0f,
                                 Wih0b, Whh0b, bih0b, bhh0b);

    dim3 gg(TQ / GM_ROWS, BQ, 2);
    gates1_gemm_kernel<<<gg, 256, GEMM_SMEM>>>(lens, Wih1f, Wih1b,
                                               bih1f, bhh1f, bih1b, bhh1b);

    lstm_l1_kernel<<<256, 256>>>(lens, Whh1f, Whh1b);

    dim3 gf(BQ / FB, 2);
    final_kernel<<<gf, 256>>>(Wout, bout, (float*)d_out);
}

// round 12
// speedup vs baseline: 1.2501x; 1.1937x over previous
#include <cuda_runtime.h>
#include <cuda_fp16.h>
#include <math.h>

#define BQ   512
#define TQ   1024
#define DQ   4
#define HQ   64
#define G4   256          // 4*H
#define NB   4            // batches per recurrent block (2 blocks/SM, paired)
#define NCLS 1098
#define FB   4            // batches per final-head block

#define HXH_STRIDE 88     // halves; conflict-free for B-frag LDS pattern
#define GP_STRIDE  6      // gpre[gate][batch] stride (float2-aligned)

// ---------------- scratch (static device allocations only) ----------------
__device__ float g_g1[2][(size_t)BQ * TQ * G4];   // layer-1 gate preactivations per dir
__device__ float g_h0[(size_t)BQ * TQ * 128];     // layer-0 bidir output, [B][T][128]
__device__ float g_h1last[BQ * 128];              // gathered last timestep of layer 1

// ---------------- helpers ----------------
__device__ __forceinline__ float tanh_fast(float x) {
    float y; asm("tanh.approx.f32 %0,%1;" : "=f"(y) : "f"(x)); return y;
}
__device__ __forceinline__ float sig_fast(float x) {
    return fmaf(0.5f, tanh_fast(0.5f * x), 0.5f);
}
__device__ __forceinline__ unsigned pack_h2(float lo, float hi) {
    __half2 h = __floats2half2_rn(lo, hi);
    return *reinterpret_cast<unsigned*>(&h);
}
// fp16 MMA, fp32 accumulate
__device__ __forceinline__ void mma_f16(float* c, const unsigned* a, unsigned b0, unsigned b1) {
    asm volatile(
        "mma.sync.aligned.m16n8k16.row.col.f32.f16.f16.f32 "
        "{%0,%1,%2,%3},{%4,%5,%6,%7},{%8,%9},{%0,%1,%2,%3};"
        : "+f"(c[0]), "+f"(c[1]), "+f"(c[2]), "+f"(c[3])
        : "r"(a[0]), "r"(a[1]), "r"(a[2]), "r"(a[3]), "r"(b0), "r"(b1));
}
// tf32 MMA (for the big GEMM)
__device__ __forceinline__ void mma_tf32(float* c, const unsigned* a, unsigned b0, unsigned b1) {
    asm volatile(
        "mma.sync.aligned.m16n8k8.row.col.f32.tf32.tf32.f32 "
        "{%0,%1,%2,%3},{%4,%5,%6,%7},{%8,%9},{%0,%1,%2,%3};"
        : "+f"(c[0]), "+f"(c[1]), "+f"(c[2]), "+f"(c[3])
        : "r"(a[0]), "r"(a[1]), "r"(a[2]), "r"(a[3]), "r"(b0), "r"(b1));
}

// block (0..255) -> sorted group id: pairs wave-1 co-resident blocks
// (bid, bid+148) with (long, short) sequence groups.
__device__ __forceinline__ void block_to_group(int bid, int& dir, int& xb) {
    int j = (bid < 148) ? bid : (403 - bid);
    dir = j & 1;
    xb  = j >> 1;
}

// =====================================================================
// Layer 0: bidirectional LSTM; fp16 tensor-core matvec + R8 exchange
// phase B (1 unit/thread, 5 MUFU, zero waste).
// D[256 gates, 8 cols(0-3 real)] = A[256 x 80] . B[80 x 8]
//   A rows = [Whh | Wih | bias | pad] fp16 reg fragments
//   B cols = hx[batch] = [h | x | 1 | pad] fp16, double-buffered
// Warp w: gates 32w..32w+31 via 2 m16 tiles. C cols 2tig,2tig+1 real
// iff tig<2 -> STS gpre; exchange barrier; phase B per (pb_b, pb_j).
// =====================================================================
__global__ void __launch_bounds__(256, 2)
lstm_l0_kernel(const float* __restrict__ x, const int* __restrict__ lens,
               const float* __restrict__ WihF, const float* __restrict__ WhhF,
               const float* __restrict__ bihF, const float* __restrict__ bhhF,
               const float* __restrict__ WihB, const float* __restrict__ WhhB,
               const float* __restrict__ bihB, const float* __restrict__ bhhB)
{
    int dir, xb;
    block_to_group(blockIdx.x, dir, xb);
    const int bbase = xb * NB;
    const int tid  = threadIdx.x;
    const int w    = tid >> 5;
    const int lane = tid & 31;
    const int gid  = lane >> 2;               // 0..7
    const int tig  = lane & 3;                // 0..3

    const float* Wih = dir ? WihB : WihF;
    const float* Whh = dir ? WhhB : WhhF;
    const float* bih = dir ? bihB : bihF;
    const float* bhh = dir ? bhhB : bhhF;

    // ---- A fragments (fp16), natural gate order, K = 80 augmented
    unsigned afr[2][5][4];
#pragma unroll
    for (int mt = 0; mt < 2; ++mt) {
#pragma unroll
        for (int kc = 0; kc < 5; ++kc) {
#pragma unroll
            for (int e = 0; e < 4; ++e) {
                int g  = w * 32 + mt * 16 + gid + ((e & 1) ? 8 : 0);
                int kb = kc * 16 + 2 * tig + ((e & 2) ? 8 : 0);
                float v0, v1;
                {
                    int k = kb;
                    v0 = (k < 64) ? Whh[g * HQ + k]
                       : (k < 68) ? Wih[g * DQ + (k - 64)]
                       : (k == 68) ? (bih[g] + bhh[g]) : 0.0f;
                }
                {
                    int k = kb + 1;
                    v1 = (k < 64) ? Whh[g * HQ + k]
                       : (k < 68) ? Wih[g * DQ + (k - 64)]
                       : (k == 68) ? (bih[g] + bhh[g]) : 0.0f;
                }
                afr[mt][kc][e] = pack_h2(v0, v1);
            }
        }
    }

    __shared__ __half hx[2][8][HXH_STRIDE];
    __shared__ float  gpre[G4 * GP_STRIDE];
    __shared__ int    lsh[NB];

    const int pb_b = tid >> 6, pb_j = tid & 63;

    if (tid < NB) lsh[tid] = lens[bbase + tid];
    for (int i = tid; i < 2 * 8 * HXH_STRIDE; i += 256)
        (&hx[0][0][0])[i] = __float2half(0.0f);
    __syncthreads();
    if (tid < 2 * NB) hx[tid >> 2][tid & 3][68] = __float2half(1.0f);  // bias lane

    const int maxlen = lsh[0];                // lens sorted descending
    float c = 0.0f;

    if (tid < NB) {
        int len = lsh[tid];
        int tt  = dir ? (len - 1) : 0;
        float4 xv = reinterpret_cast<const float4*>(x)[(size_t)(bbase + tid) * TQ + tt];
        hx[0][tid][64] = __float2half(xv.x); hx[0][tid][65] = __float2half(xv.y);
        hx[0][tid][66] = __float2half(xv.z); hx[0][tid][67] = __float2half(xv.w);
    }
    __syncthreads();

    for (int t = 0; t < maxlen; ++t) {
        const int buf = t & 1, nbuf = buf ^ 1;

        // prefetch x(t+1) (overlaps MMA)
        float4 xn = make_float4(0.f, 0.f, 0.f, 0.f);
        if (tid < NB) {
            int tn  = (t + 1 < maxlen) ? (t + 1) : t;
            int len = lsh[tid];
            int tt  = dir ? ((tn < len) ? (len - 1 - tn) : tn) : tn;
            xn = reinterpret_cast<const float4*>(x)[(size_t)(bbase + tid) * TQ + tt];
        }

        // ---- phase A: fp16 tensor-core matvec (5 K-chunks, 2 tiles)
        const __half* hxb = &hx[buf][gid][0];
        float a0[4] = {0.f, 0.f, 0.f, 0.f}, a1[4] = {0.f, 0.f, 0.f, 0.f};
#pragma unroll
        for (int kc = 0; kc < 5; ++kc) {
            unsigned p = *reinterpret_cast<const unsigned*>(&hxb[kc * 16 + 2 * tig]);
            unsigned q = *reinterpret_cast<const unsigned*>(&hxb[kc * 16 + 2 * tig + 8]);
            mma_f16(a0, afr[0][kc], p, q);
            mma_f16(a1, afr[1][kc], p, q);
        }
        if (tig < 2) {
            int g0 = w * 32 + gid;
            *reinterpret_cast<float2*>(&gpre[g0 * GP_STRIDE + 2 * tig]) =
                make_float2(a0[0], a0[1]);
            *reinterpret_cast<float2*>(&gpre[(g0 + 8) * GP_STRIDE + 2 * tig]) =
                make_float2(a0[2], a0[3]);
            *reinterpret_cast<float2*>(&gpre[(g0 + 16) * GP_STRIDE + 2 * tig]) =
                make_float2(a1[0], a1[1]);
            *reinterpret_cast<float2*>(&gpre[(g0 + 24) * GP_STRIDE + 2 * tig]) =
                make_float2(a1[2], a1[3]);
        }
        __syncthreads();

        // ---- phase B: pointwise cell update for (pb_b, pb_j)
        {
            float gi = gpre[(pb_j)       * GP_STRIDE + pb_b];
            float gf = gpre[(64  + pb_j) * GP_STRIDE + pb_b];
            float gc = gpre[(128 + pb_j) * GP_STRIDE + pb_b];
            float go = gpre[(192 + pb_j) * GP_STRIDE + pb_b];
            float si = sig_fast(gi);
            float sf = sig_fast(gf);
            float tg = tanh_fast(gc);
            float so = sig_fast(go);
            c = sf * c + si * tg;
            float h = so * tanh_fast(c);
            hx[nbuf][pb_b][pb_j] = __float2half_rn(h);

            int len = lsh[pb_b];
            int ts  = dir ? ((t < len) ? (len - 1 - t) : t) : t;
            g_h0[((size_t)(bbase + pb_b) * TQ + ts) * 128 + dir * HQ + pb_j] = h;
        }
        if (tid < NB) {
            hx[nbuf][tid][64] = __float2half(xn.x);
            hx[nbuf][tid][65] = __float2half(xn.y);
            hx[nbuf][tid][66] = __float2half(xn.z);
            hx[nbuf][tid][67] = __float2half(xn.w);
        }
        __syncthreads();
    }
}

// =====================================================================
// Layer-1 gate GEMM on tensor cores (R7 tf32, unchanged).
// =====================================================================
#define GM_ROWS   64
#define AS_STRIDE 132
#define WS_STRIDE 36
#define GEMM_SMEM ((64 * AS_STRIDE + 256 * WS_STRIDE) * 4)   // 70656 B

__global__ void __launch_bounds__(256, 2)
gates1_gemm_kernel(const int* __restrict__ lens,
                   const float* __restrict__ WihF, const float* __restrict__ WihB,
                   const float* __restrict__ bihF, const float* __restrict__ bhhF,
                   const float* __restrict__ bihB, const float* __restrict__ bhhB)
{
    const int tile  = blockIdx.x;
    const int b     = blockIdx.y;
    const int dir   = blockIdx.z;
    const int tbase = tile * GM_ROWS;

    const int len = lens[b];
    if (tbase >= len) return;

    extern __shared__ float sm[];
    float* As = sm;
    float* Ws = sm + 64 * AS_STRIDE;

    const int tid  = threadIdx.x;
    const int lane = tid & 31;
    const int w    = tid >> 5;
    const int wr   = w & 3;
    const int wc   = w >> 2;
    const int gid  = lane >> 2;
    const int tig  = lane & 3;

    const float* Wih = dir ? WihB : WihF;
    const float* bih = dir ? bihB : bihF;
    const float* bhh = dir ? bhhB : bhhF;

    float acc[16][4];
#pragma unroll
    for (int nt = 0; nt < 16; ++nt) {
        int col0 = wc * 128 + nt * 8 + 2 * tig;
        float bv0 = bih[col0]     + bhh[col0];
        float bv1 = bih[col0 + 1] + bhh[col0 + 1];
        acc[nt][0] = bv0; acc[nt][1] = bv1;
        acc[nt][2] = bv0; acc[nt][3] = bv1;
    }

    const float* h0b = g_h0 + (size_t)b * TQ * 128;
#pragma unroll
    for (int i = 0; i < 8; ++i) {
        int idx = tid + 256 * i;
        int r   = idx >> 5, kq = idx & 31;
        int srow = tbase + r;
        if (dir) srow = (srow < len) ? (len - 1 - srow) : srow;
        float4 v = *reinterpret_cast<const float4*>(h0b + (size_t)srow * 128 + 4 * kq);
        *reinterpret_cast<float4*>(&As[r * AS_STRIDE + 4 * kq]) = v;
    }

    const int r0 = wr * 16 + gid;

    for (int k0 = 0; k0 < 128; k0 += 32) {
        __syncthreads();
#pragma unroll
        for (int i = 0; i < 8; ++i) {
            int idx = tid + 256 * i;
            int n   = idx >> 3, kq = idx & 7;
            float4 v = *reinterpret_cast<const float4*>(Wih + (size_t)n * 128 + k0 + 4 * kq);
            *reinterpret_cast<float4*>(&Ws[n * WS_STRIDE + 4 * kq]) = v;
        }
        __syncthreads();

#pragma unroll
        for (int ks = 0; ks < 4; ++ks) {
            const int kl = ks * 8;
            unsigned a[4];
            a[0] = __float_as_uint(As[r0 * AS_STRIDE + k0 + kl + tig]);
            a[1] = __float_as_uint(As[(r0 + 8) * AS_STRIDE + k0 + kl + tig]);
            a[2] = __float_as_uint(As[r0 * AS_STRIDE + k0 + kl + 4 + tig]);
            a[3] = __float_as_uint(As[(r0 + 8) * AS_STRIDE + k0 + kl + 4 + tig]);
#pragma unroll
            for (int nt = 0; nt < 16; ++nt) {
                int n = wc * 128 + nt * 8 + gid;
                unsigned b0 = __float_as_uint(Ws[n * WS_STRIDE + kl + tig]);
                unsigned b1 = __float_as_uint(Ws[n * WS_STRIDE + kl + 4 + tig]);
                mma_tf32(acc[nt], a, b0, b1);
            }
        }
    }

    float* outp = g_g1[dir] + ((size_t)b * TQ + tbase) * G4;
#pragma unroll
    for (int nt = 0; nt < 16; ++nt) {
        int col0 = wc * 128 + nt * 8 + 2 * tig;
        *reinterpret_cast<float2*>(outp + (size_t)r0 * G4 + col0) =
            make_float2(acc[nt][0], acc[nt][1]);
        *reinterpret_cast<float2*>(outp + (size_t)(r0 + 8) * G4 + col0) =
            make_float2(acc[nt][2], acc[nt][3]);
    }
}

// =====================================================================
// Layer 1: recurrent over precomputed gates; fp16 MMA (K=64) + R8
// exchange phase B with per-thread preact streams.
// =====================================================================
__global__ void __launch_bounds__(256, 2)
lstm_l1_kernel(const int* __restrict__ lens,
               const float* __restrict__ WhhF, const float* __restrict__ WhhB)
{
    int dir, xb;
    block_to_group(blockIdx.x, dir, xb);
    const int bbase = xb * NB;
    const int tid  = threadIdx.x;
    const int w    = tid >> 5;
    const int lane = tid & 31;
    const int gid  = lane >> 2;
    const int tig  = lane & 3;

    const float* Whh = dir ? WhhB : WhhF;
    const float* gin = g_g1[dir];

    // ---- A fragments (fp16), natural gate order, K = 64
    unsigned afr[2][4][4];
#pragma unroll
    for (int mt = 0; mt < 2; ++mt) {
#pragma unroll
        for (int kc = 0; kc < 4; ++kc) {
#pragma unroll
            for (int e = 0; e < 4; ++e) {
                int g  = w * 32 + mt * 16 + gid + ((e & 1) ? 8 : 0);
                int kb = kc * 16 + 2 * tig + ((e & 2) ? 8 : 0);
                afr[mt][kc][e] = pack_h2(Whh[g * HQ + kb], Whh[g * HQ + kb + 1]);
            }
        }
    }

    __shared__ __half hx[2][8][HXH_STRIDE];
    __shared__ float  gpre[G4 * GP_STRIDE];
    __shared__ int    lsh[NB];

    const int pb_b = tid >> 6, pb_j = tid & 63;
    if (tid < NB) lsh[tid] = lens[bbase + tid];
    for (int i = tid; i < 2 * 8 * HXH_STRIDE; i += 256)
        (&hx[0][0][0])[i] = __float2half(0.0f);
    float c = 0.0f;
    __syncthreads();

    const int maxlen = lsh[0];

    // per-thread preact stream for phase-B role (pb_b, pb_j)
    const float* gsrc = gin + (size_t)(bbase + pb_b) * TQ * G4 + pb_j;

    float ldc[4];
#pragma unroll
    for (int q = 0; q < 4; ++q) ldc[q] = gsrc[q * 64];

    for (int t = 0; t < maxlen; ++t) {
        const int buf = t & 1, nbuf = buf ^ 1;

        // prefetch next-step preacts (overlaps MMA)
        float ldn[4];
        const int tn = (t + 1 < maxlen) ? (t + 1) : t;
#pragma unroll
        for (int q = 0; q < 4; ++q) ldn[q] = gsrc[(size_t)tn * G4 + q * 64];

        // ---- phase A: fp16 tensor-core matvec (4 K-chunks, 2 tiles)
        const __half* hxb = &hx[buf][gid][0];
        float a0[4] = {0.f, 0.f, 0.f, 0.f}, a1[4] = {0.f, 0.f, 0.f, 0.f};
#pragma unroll
        for (int kc = 0; kc < 4; ++kc) {
            unsigned p = *reinterpret_cast<const unsigned*>(&hxb[kc * 16 + 2 * tig]);
            unsigned q = *reinterpret_cast<const unsigned*>(&hxb[kc * 16 + 2 * tig + 8]);
            mma_f16(a0, afr[0][kc], p, q);
            mma_f16(a1, afr[1][kc], p, q);
        }
        if (tig < 2) {
            int g0 = w * 32 + gid;
            *reinterpret_cast<float2*>(&gpre[g0 * GP_STRIDE + 2 * tig]) =
                make_float2(a0[0], a0[1]);
            *reinterpret_cast<float2*>(&gpre[(g0 + 8) * GP_STRIDE + 2 * tig]) =
                make_float2(a0[2], a0[3]);
            *reinterpret_cast<float2*>(&gpre[(g0 + 16) * GP_STRIDE + 2 * tig]) =
                make_float2(a1[0], a1[1]);
            *reinterpret_cast<float2*>(&gpre[(g0 + 24) * GP_STRIDE + 2 * tig]) =
                make_float2(a1[2], a1[3]);
        }
        __syncthreads();

        // ---- phase B: pointwise for (pb_b, pb_j), preacts added here
        {
            float gi = gpre[(pb_j)       * GP_STRIDE + pb_b] + ldc[0];
            float gf = gpre[(64  + pb_j) * GP_STRIDE + pb_b] + ldc[1];
            float gc = gpre[(128 + pb_j) * GP_STRIDE + pb_b] + ldc[2];
            float go = gpre[(192 + pb_j) * GP_STRIDE + pb_b] + ldc[3];
            float si = sig_fast(gi);
            float sf = sig_fast(gf);
            float tg = tanh_fast(gc);
            float so = sig_fast(go);
            c = sf * c + si * tg;
            float h = so * tanh_fast(c);
            hx[nbuf][pb_b][pb_j] = __float2half_rn(h);

            int  len = lsh[pb_b];
            bool wr  = dir ? (t == 0) : (t == len - 1);
            if (wr)
                g_h1last[(bbase + pb_b) * 128 + dir * HQ + pb_j] = h;
        }
#pragma unroll
        for (int q = 0; q < 4; ++q) ldc[q] = ldn[q];
        __syncthreads();
    }
}

// =====================================================================
// Final head: FB=4 batches per block; class range split in 2.
// =====================================================================
__global__ void __launch_bounds__(256)
final_kernel(const float* __restrict__ Wout, const float* __restrict__ bout,
             float* __restrict__ out)
{
    const int bbase = blockIdx.x * FB;
    const int chalf = blockIdx.y;
    __shared__ float hs[FB][128];
    for (int i = threadIdx.x; i < FB * 128; i += 256)
        hs[i >> 7][i & 127] = g_h1last[bbase * 128 + i];
    __syncthreads();

    const int cbeg = chalf * 549;
    const int cend = cbeg + 549;
    for (int cl = cbeg + threadIdx.x; cl < cend; cl += 256) {
        const float4* wv = reinterpret_cast<const float4*>(Wout + (size_t)cl * 128);
        float a[FB];
#pragma unroll
        for (int b = 0; b < FB; ++b) a[b] = bout[cl];
#pragma unroll
        for (int k = 0; k < 32; ++k) {
            float4 v = wv[k];
#pragma unroll
            for (int b = 0; b < FB; ++b) {
                a[b] += hs[b][4 * k + 0] * v.x + hs[b][4 * k + 1] * v.y
                      + hs[b][4 * k + 2] * v.z + hs[b][4 * k + 3] * v.w;
            }
        }
#pragma unroll
        for (int b = 0; b < FB; ++b)
            out[(size_t)(bbase + b) * NCLS + cl] = a[b];
    }
}

// =====================================================================
extern "C" void kernel_launch(void* const* d_in, const int* in_sizes, int n_in,
                              void* d_out, int out_size)
{
    const float* x     = (const float*)d_in[0];
    const int*   lens  = (const int*)  d_in[1];
    const float* Wih0f = (const float*)d_in[2];
    const float* Whh0f = (const float*)d_in[3];
    const float* bih0f = (const float*)d_in[4];
    const float* bhh0f = (const float*)d_in[5];
    const float* Wih0b = (const float*)d_in[6];
    const float* Whh0b = (const float*)d_in[7];
    const float* bih0b = (const float*)d_in[8];
    const float* bhh0b = (const float*)d_in[9];
    const float* Wih1f = (const float*)d_in[10];
    const float* Whh1f = (const float*)d_in[11];
    const float* bih1f = (const float*)d_in[12];
    const float* bhh1f = (const float*)d_in[13];
    const float* Wih1b = (const float*)d_in[14];
    const float* Whh1b = (const float*)d_in[15];
    const float* bih1b = (const float*)d_in[16];
    const float* bhh1b = (const float*)d_in[17];
    const float* Wout  = (const float*)d_in[18];
    const float* bout  = (const float*)d_in[19];

    static bool attr_set = false;
    if (!attr_set) {
        cudaFuncSetAttribute(gates1_gemm_kernel,
                             cudaFuncAttributeMaxDynamicSharedMemorySize, GEMM_SMEM);
        attr_set = true;
    }

    lstm_l0_kernel<<<256, 256>>>(x, lens,
                                 Wih0f, Whh0f, bih0f, bhh0f,
                                 Wih0b, Whh0b, bih0b, bhh0b);

    dim3 gg(TQ / GM_ROWS, BQ, 2);
    gates1_gemm_kernel<<<gg, 256, GEMM_SMEM>>>(lens, Wih1f, Wih1b,
                                               bih1f, bhh1f, bih1b, bhh1b);

    lstm_l1_kernel<<<256, 256>>>(lens, Whh1f, Whh1b);

    dim3 gf(BQ / FB, 2);
    final_kernel<<<gf, 256>>>(Wout, bout, (float*)d_out);
}

// round 13
// speedup vs baseline: 1.3722x; 1.0977x over previous
#include <cuda_runtime.h>
#include <cuda_fp16.h>
#include <math.h>

#define BQ   512
#define TQ   1024
#define DQ   4
#define HQ   64
#define G4   256          // 4*H
#define NB   4            // batches per recurrent block (2 blocks/SM, paired)
#define NCLS 1098
#define FB   4            // batches per final-head block

#define HXH_STRIDE 88     // halves; conflict-free for B-frag LDS pattern
#define GP_STRIDE  6      // gpre[gate][batch] stride (float2-aligned)

// ---------------- scratch (static device allocations only) ----------------
__device__ float  g_g1[2][(size_t)BQ * TQ * G4];  // layer-1 gate preactivations per dir
__device__ __half g_h0[(size_t)BQ * TQ * 128];    // layer-0 bidir output (fp16), [B][T][128]
__device__ float  g_h1last[BQ * 128];             // gathered last timestep of layer 1

// ---------------- helpers ----------------
__device__ __forceinline__ float tanh_fast(float x) {
    float y; asm("tanh.approx.f32 %0,%1;" : "=f"(y) : "f"(x)); return y;
}
__device__ __forceinline__ float sig_fast(float x) {
    return fmaf(0.5f, tanh_fast(0.5f * x), 0.5f);
}
__device__ __forceinline__ unsigned pack_h2(float lo, float hi) {
    __half2 h = __floats2half2_rn(lo, hi);
    return *reinterpret_cast<unsigned*>(&h);
}
// fp16 MMA, fp32 accumulate
__device__ __forceinline__ void mma_f16(float* c, const unsigned* a, unsigned b0, unsigned b1) {
    asm volatile(
        "mma.sync.aligned.m16n8k16.row.col.f32.f16.f16.f32 "
        "{%0,%1,%2,%3},{%4,%5,%6,%7},{%8,%9},{%0,%1,%2,%3};"
        : "+f"(c[0]), "+f"(c[1]), "+f"(c[2]), "+f"(c[3])
        : "r"(a[0]), "r"(a[1]), "r"(a[2]), "r"(a[3]), "r"(b0), "r"(b1));
}

// block (0..255) -> sorted group id: pairs wave-1 co-resident blocks
// (bid, bid+148) with (long, short) sequence groups.
__device__ __forceinline__ void block_to_group(int bid, int& dir, int& xb) {
    int j = (bid < 148) ? bid : (403 - bid);
    dir = j & 1;
    xb  = j >> 1;
}

// =====================================================================
// Layer 0: bidirectional LSTM; fp16 tensor-core matvec + exchange
// phase B (1 unit/thread). Unchanged from R12 except fp16 g_h0 store.
// =====================================================================
__global__ void __launch_bounds__(256, 2)
lstm_l0_kernel(const float* __restrict__ x, const int* __restrict__ lens,
               const float* __restrict__ WihF, const float* __restrict__ WhhF,
               const float* __restrict__ bihF, const float* __restrict__ bhhF,
               const float* __restrict__ WihB, const float* __restrict__ WhhB,
               const float* __restrict__ bihB, const float* __restrict__ bhhB)
{
    int dir, xb;
    block_to_group(blockIdx.x, dir, xb);
    const int bbase = xb * NB;
    const int tid  = threadIdx.x;
    const int w    = tid >> 5;
    const int lane = tid & 31;
    const int gid  = lane >> 2;               // 0..7
    const int tig  = lane & 3;                // 0..3

    const float* Wih = dir ? WihB : WihF;
    const float* Whh = dir ? WhhB : WhhF;
    const float* bih = dir ? bihB : bihF;
    const float* bhh = dir ? bhhB : bhhF;

    // ---- A fragments (fp16), natural gate order, K = 80 augmented
    unsigned afr[2][5][4];
#pragma unroll
    for (int mt = 0; mt < 2; ++mt) {
#pragma unroll
        for (int kc = 0; kc < 5; ++kc) {
#pragma unroll
            for (int e = 0; e < 4; ++e) {
                int g  = w * 32 + mt * 16 + gid + ((e & 1) ? 8 : 0);
                int kb = kc * 16 + 2 * tig + ((e & 2) ? 8 : 0);
                float v0, v1;
                {
                    int k = kb;
                    v0 = (k < 64) ? Whh[g * HQ + k]
                       : (k < 68) ? Wih[g * DQ + (k - 64)]
                       : (k == 68) ? (bih[g] + bhh[g]) : 0.0f;
                }
                {
                    int k = kb + 1;
                    v1 = (k < 64) ? Whh[g * HQ + k]
                       : (k < 68) ? Wih[g * DQ + (k - 64)]
                       : (k == 68) ? (bih[g] + bhh[g]) : 0.0f;
                }
                afr[mt][kc][e] = pack_h2(v0, v1);
            }
        }
    }

    __shared__ __half hx[2][8][HXH_STRIDE];
    __shared__ float  gpre[G4 * GP_STRIDE];
    __shared__ int    lsh[NB];

    const int pb_b = tid >> 6, pb_j = tid & 63;

    if (tid < NB) lsh[tid] = lens[bbase + tid];
    for (int i = tid; i < 2 * 8 * HXH_STRIDE; i += 256)
        (&hx[0][0][0])[i] = __float2half(0.0f);
    __syncthreads();
    if (tid < 2 * NB) hx[tid >> 2][tid & 3][68] = __float2half(1.0f);  // bias lane

    const int maxlen = lsh[0];                // lens sorted descending
    float c = 0.0f;

    if (tid < NB) {
        int len = lsh[tid];
        int tt  = dir ? (len - 1) : 0;
        float4 xv = reinterpret_cast<const float4*>(x)[(size_t)(bbase + tid) * TQ + tt];
        hx[0][tid][64] = __float2half(xv.x); hx[0][tid][65] = __float2half(xv.y);
        hx[0][tid][66] = __float2half(xv.z); hx[0][tid][67] = __float2half(xv.w);
    }
    __syncthreads();

    for (int t = 0; t < maxlen; ++t) {
        const int buf = t & 1, nbuf = buf ^ 1;

        // prefetch x(t+1) (overlaps MMA)
        float4 xn = make_float4(0.f, 0.f, 0.f, 0.f);
        if (tid < NB) {
            int tn  = (t + 1 < maxlen) ? (t + 1) : t;
            int len = lsh[tid];
            int tt  = dir ? ((tn < len) ? (len - 1 - tn) : tn) : tn;
            xn = reinterpret_cast<const float4*>(x)[(size_t)(bbase + tid) * TQ + tt];
        }

        // ---- phase A: fp16 tensor-core matvec (5 K-chunks, 2 tiles)
        const __half* hxb = &hx[buf][gid][0];
        float a0[4] = {0.f, 0.f, 0.f, 0.f}, a1[4] = {0.f, 0.f, 0.f, 0.f};
#pragma unroll
        for (int kc = 0; kc < 5; ++kc) {
            unsigned p = *reinterpret_cast<const unsigned*>(&hxb[kc * 16 + 2 * tig]);
            unsigned q = *reinterpret_cast<const unsigned*>(&hxb[kc * 16 + 2 * tig + 8]);
            mma_f16(a0, afr[0][kc], p, q);
            mma_f16(a1, afr[1][kc], p, q);
        }
        if (tig < 2) {
            int g0 = w * 32 + gid;
            *reinterpret_cast<float2*>(&gpre[g0 * GP_STRIDE + 2 * tig]) =
                make_float2(a0[0], a0[1]);
            *reinterpret_cast<float2*>(&gpre[(g0 + 8) * GP_STRIDE + 2 * tig]) =
                make_float2(a0[2], a0[3]);
            *reinterpret_cast<float2*>(&gpre[(g0 + 16) * GP_STRIDE + 2 * tig]) =
                make_float2(a1[0], a1[1]);
            *reinterpret_cast<float2*>(&gpre[(g0 + 24) * GP_STRIDE + 2 * tig]) =
                make_float2(a1[2], a1[3]);
        }
        __syncthreads();

        // ---- phase B: pointwise cell update for (pb_b, pb_j)
        {
            float gi = gpre[(pb_j)       * GP_STRIDE + pb_b];
            float gf = gpre[(64  + pb_j) * GP_STRIDE + pb_b];
            float gc = gpre[(128 + pb_j) * GP_STRIDE + pb_b];
            float go = gpre[(192 + pb_j) * GP_STRIDE + pb_b];
            float si = sig_fast(gi);
            float sf = sig_fast(gf);
            float tg = tanh_fast(gc);
            float so = sig_fast(go);
            c = sf * c + si * tg;
            float h = so * tanh_fast(c);
            __half hh = __float2half_rn(h);
            hx[nbuf][pb_b][pb_j] = hh;

            int len = lsh[pb_b];
            int ts  = dir ? ((t < len) ? (len - 1 - t) : t) : t;
            g_h0[((size_t)(bbase + pb_b) * TQ + ts) * 128 + dir * HQ + pb_j] = hh;
        }
        if (tid < NB) {
            hx[nbuf][tid][64] = __float2half(xn.x);
            hx[nbuf][tid][65] = __float2half(xn.y);
            hx[nbuf][tid][66] = __float2half(xn.z);
            hx[nbuf][tid][67] = __float2half(xn.w);
        }
        __syncthreads();
    }
}

// =====================================================================
// Layer-1 gate GEMM on fp16 tensor cores (m16n8k16).
//   C[64 rows][256 gates] = A[64x128 fp16 h0] . W^T (fp16, whole-W smem)
// One staging phase + ONE barrier; 128 HMMA/warp. Bias in C init.
// =====================================================================
#define GM_ROWS   64
#define ASH_STRIDE 136      // halves (272 B) -> conflict-free frags
#define WSH_STRIDE 136
#define GEMM_SMEM ((GM_ROWS * ASH_STRIDE + G4 * WSH_STRIDE) * 2)   // 87040 B

__global__ void __launch_bounds__(256, 2)
gates1_gemm_kernel(const int* __restrict__ lens,
                   const float* __restrict__ WihF, const float* __restrict__ WihB,
                   const float* __restrict__ bihF, const float* __restrict__ bhhF,
                   const float* __restrict__ bihB, const float* __restrict__ bhhB)
{
    const int tile  = blockIdx.x;
    const int b     = blockIdx.y;
    const int dir   = blockIdx.z;
    const int tbase = tile * GM_ROWS;

    const int len = lens[b];
    if (tbase >= len) return;

    extern __shared__ __half smh[];
    __half* As = smh;                          // [64][ASH_STRIDE]
    __half* Ws = smh + GM_ROWS * ASH_STRIDE;   // [256][WSH_STRIDE]

    const int tid  = threadIdx.x;
    const int lane = tid & 31;
    const int w    = tid >> 5;
    const int wr   = w & 3;
    const int wc   = w >> 2;
    const int gid  = lane >> 2;
    const int tig  = lane & 3;

    const float* Wih = dir ? WihB : WihF;
    const float* bih = dir ? bihB : bihF;
    const float* bhh = dir ? bhhB : bhhF;

    float acc[16][4];
#pragma unroll
    for (int nt = 0; nt < 16; ++nt) {
        int col0 = wc * 128 + nt * 8 + 2 * tig;
        float bv0 = bih[col0]     + bhh[col0];
        float bv1 = bih[col0 + 1] + bhh[col0 + 1];
        acc[nt][0] = bv0; acc[nt][1] = bv1;
        acc[nt][2] = bv0; acc[nt][3] = bv1;
    }

    // ---- A tile: 64 rows x 128 halves (16B chunks), backward row gather
    const __half* h0b = g_h0 + (size_t)b * TQ * 128;
#pragma unroll
    for (int i = 0; i < 4; ++i) {
        int idx = tid + 256 * i;              // 0..1023 uint4 slots (8 halves)
        int r   = idx >> 4, kq = idx & 15;
        int srow = tbase + r;
        if (dir) srow = (srow < len) ? (len - 1 - srow) : srow;
        uint4 v = *reinterpret_cast<const uint4*>(h0b + (size_t)srow * 128 + 8 * kq);
        *reinterpret_cast<uint4*>(&As[r * ASH_STRIDE + 8 * kq]) = v;
    }

    // ---- W tile: 256 gates x 128, fp32 -> fp16 convert on stage
#pragma unroll
    for (int i = 0; i < 32; ++i) {
        int idx = tid + 256 * i;              // 0..8191 float4 slots
        int n   = idx >> 5, kq = idx & 31;
        float4 v = *reinterpret_cast<const float4*>(Wih + (size_t)n * 128 + 4 * kq);
        __half2 lo = __floats2half2_rn(v.x, v.y);
        __half2 hi = __floats2half2_rn(v.z, v.w);
        *reinterpret_cast<__half2*>(&Ws[n * WSH_STRIDE + 4 * kq])     = lo;
        *reinterpret_cast<__half2*>(&Ws[n * WSH_STRIDE + 4 * kq + 2]) = hi;
    }
    __syncthreads();

    const int r0 = wr * 16 + gid;

#pragma unroll
    for (int kc = 0; kc < 8; ++kc) {
        const int kl = kc * 16;
        unsigned a[4];
        a[0] = *reinterpret_cast<const unsigned*>(&As[r0 * ASH_STRIDE + kl + 2 * tig]);
        a[1] = *reinterpret_cast<const unsigned*>(&As[(r0 + 8) * ASH_STRIDE + kl + 2 * tig]);
        a[2] = *reinterpret_cast<const unsigned*>(&As[r0 * ASH_STRIDE + kl + 2 * tig + 8]);
        a[3] = *reinterpret_cast<const unsigned*>(&As[(r0 + 8) * ASH_STRIDE + kl + 2 * tig + 8]);
#pragma unroll
        for (int nt = 0; nt < 16; ++nt) {
            int n = wc * 128 + nt * 8 + gid;
            unsigned b0 = *reinterpret_cast<const unsigned*>(&Ws[n * WSH_STRIDE + kl + 2 * tig]);
            unsigned b1 = *reinterpret_cast<const unsigned*>(&Ws[n * WSH_STRIDE + kl + 2 * tig + 8]);
            mma_f16(acc[nt], a, b0, b1);
        }
    }

    float* outp = g_g1[dir] + ((size_t)b * TQ + tbase) * G4;
#pragma unroll
    for (int nt = 0; nt < 16; ++nt) {
        int col0 = wc * 128 + nt * 8 + 2 * tig;
        *reinterpret_cast<float2*>(outp + (size_t)r0 * G4 + col0) =
            make_float2(acc[nt][0], acc[nt][1]);
        *reinterpret_cast<float2*>(outp + (size_t)(r0 + 8) * G4 + col0) =
            make_float2(acc[nt][2], acc[nt][3]);
    }
}

// =====================================================================
// Layer 1: recurrent over precomputed gates; fp16 MMA (K=64) + exchange
// phase B with per-thread preact streams. (R12, unchanged)
// =====================================================================
__global__ void __launch_bounds__(256, 2)
lstm_l1_kernel(const int* __restrict__ lens,
               const float* __restrict__ WhhF, const float* __restrict__ WhhB)
{
    int dir, xb;
    block_to_group(blockIdx.x, dir, xb);
    const int bbase = xb * NB;
    const int tid  = threadIdx.x;
    const int w    = tid >> 5;
    const int lane = tid & 31;
    const int gid  = lane >> 2;
    const int tig  = lane & 3;

    const float* Whh = dir ? WhhB : WhhF;
    const float* gin = g_g1[dir];

    // ---- A fragments (fp16), natural gate order, K = 64
    unsigned afr[2][4][4];
#pragma unroll
    for (int mt = 0; mt < 2; ++mt) {
#pragma unroll
        for (int kc = 0; kc < 4; ++kc) {
#pragma unroll
            for (int e = 0; e < 4; ++e) {
                int g  = w * 32 + mt * 16 + gid + ((e & 1) ? 8 : 0);
                int kb = kc * 16 + 2 * tig + ((e & 2) ? 8 : 0);
                afr[mt][kc][e] = pack_h2(Whh[g * HQ + kb], Whh[g * HQ + kb + 1]);
            }
        }
    }

    __shared__ __half hx[2][8][HXH_STRIDE];
    __shared__ float  gpre[G4 * GP_STRIDE];
    __shared__ int    lsh[NB];

    const int pb_b = tid >> 6, pb_j = tid & 63;
    if (tid < NB) lsh[tid] = lens[bbase + tid];
    for (int i = tid; i < 2 * 8 * HXH_STRIDE; i += 256)
        (&hx[0][0][0])[i] = __float2half(0.0f);
    float c = 0.0f;
    __syncthreads();

    const int maxlen = lsh[0];

    // per-thread preact stream for phase-B role (pb_b, pb_j)
    const float* gsrc = gin + (size_t)(bbase + pb_b) * TQ * G4 + pb_j;

    float ldc[4];
#pragma unroll
    for (int q = 0; q < 4; ++q) ldc[q] = gsrc[q * 64];

    for (int t = 0; t < maxlen; ++t) {
        const int buf = t & 1, nbuf = buf ^ 1;

        // prefetch next-step preacts (overlaps MMA)
        float ldn[4];
        const int tn = (t + 1 < maxlen) ? (t + 1) : t;
#pragma unroll
        for (int q = 0; q < 4; ++q) ldn[q] = gsrc[(size_t)tn * G4 + q * 64];

        // ---- phase A: fp16 tensor-core matvec (4 K-chunks, 2 tiles)
        const __half* hxb = &hx[buf][gid][0];
        float a0[4] = {0.f, 0.f, 0.f, 0.f}, a1[4] = {0.f, 0.f, 0.f, 0.f};
#pragma unroll
        for (int kc = 0; kc < 4; ++kc) {
            unsigned p = *reinterpret_cast<const unsigned*>(&hxb[kc * 16 + 2 * tig]);
            unsigned q = *reinterpret_cast<const unsigned*>(&hxb[kc * 16 + 2 * tig + 8]);
            mma_f16(a0, afr[0][kc], p, q);
            mma_f16(a1, afr[1][kc], p, q);
        }
        if (tig < 2) {
            int g0 = w * 32 + gid;
            *reinterpret_cast<float2*>(&gpre[g0 * GP_STRIDE + 2 * tig]) =
                make_float2(a0[0], a0[1]);
            *reinterpret_cast<float2*>(&gpre[(g0 + 8) * GP_STRIDE + 2 * tig]) =
                make_float2(a0[2], a0[3]);
            *reinterpret_cast<float2*>(&gpre[(g0 + 16) * GP_STRIDE + 2 * tig]) =
                make_float2(a1[0], a1[1]);
            *reinterpret_cast<float2*>(&gpre[(g0 + 24) * GP_STRIDE + 2 * tig]) =
                make_float2(a1[2], a1[3]);
        }
        __syncthreads();

        // ---- phase B: pointwise for (pb_b, pb_j), preacts added here
        {
            float gi = gpre[(pb_j)       * GP_STRIDE + pb_b] + ldc[0];
            float gf = gpre[(64  + pb_j) * GP_STRIDE + pb_b] + ldc[1];
            float gc = gpre[(128 + pb_j) * GP_STRIDE + pb_b] + ldc[2];
            float go = gpre[(192 + pb_j) * GP_STRIDE + pb_b] + ldc[3];
            float si = sig_fast(gi);
            float sf = sig_fast(gf);
            float tg = tanh_fast(gc);
            float so = sig_fast(go);
            c = sf * c + si * tg;
            float h = so * tanh_fast(c);
            hx[nbuf][pb_b][pb_j] = __float2half_rn(h);

            int  len = lsh[pb_b];
            bool wr  = dir ? (t == 0) : (t == len - 1);
            if (wr)
                g_h1last[(bbase + pb_b) * 128 + dir * HQ + pb_j] = h;
        }
#pragma unroll
        for (int q = 0; q < 4; ++q) ldc[q] = ldn[q];
        __syncthreads();
    }
}

// =====================================================================
// Final head: FB=4 batches per block; class range split in 4.
// =====================================================================
__global__ void __launch_bounds__(256)
final_kernel(const float* __restrict__ Wout, const float* __restrict__ bout,
             float* __restrict__ out)
{
    const int bbase = blockIdx.x * FB;
    const int cpart = blockIdx.y;              // 0..3
    __shared__ float hs[FB][128];
    for (int i = threadIdx.x; i < FB * 128; i += 256)
        hs[i >> 7][i & 127] = g_h1last[bbase * 128 + i];
    __syncthreads();

    const int cbeg = cpart * 275;
    const int cend = (cbeg + 275 < NCLS) ? (cbeg + 275) : NCLS;
    for (int cl = cbeg + threadIdx.x; cl < cend; cl += 256) {
        const float4* wv = reinterpret_cast<const float4*>(Wout + (size_t)cl * 128);
        float a[FB];
#pragma unroll
        for (int b = 0; b < FB; ++b) a[b] = bout[cl];
#pragma unroll
        for (int k = 0; k < 32; ++k) {
            float4 v = wv[k];
#pragma unroll
            for (int b = 0; b < FB; ++b) {
                a[b] += hs[b][4 * k + 0] * v.x + hs[b][4 * k + 1] * v.y
                      + hs[b][4 * k + 2] * v.z + hs[b][4 * k + 3] * v.w;
            }
        }
#pragma unroll
        for (int b = 0; b < FB; ++b)
            out[(size_t)(bbase + b) * NCLS + cl] = a[b];
    }
}

// =====================================================================
extern "C" void kernel_launch(void* const* d_in, const int* in_sizes, int n_in,
                              void* d_out, int out_size)
{
    const float* x     = (const float*)d_in[0];
    const int*   lens  = (const int*)  d_in[1];
    const float* Wih0f = (const float*)d_in[2];
    const float* Whh0f = (const float*)d_in[3];
    const float* bih0f = (const float*)d_in[4];
    const float* bhh0f = (const float*)d_in[5];
    const float* Wih0b = (const float*)d_in[6];
    const float* Whh0b = (const float*)d_in[7];
    const float* bih0b = (const float*)d_in[8];
    const float* bhh0b = (const float*)d_in[9];
    const float* Wih1f = (const float*)d_in[10];
    const float* Whh1f = (const float*)d_in[11];
    const float* bih1f = (const float*)d_in[12];
    const float* bhh1f = (const float*)d_in[13];
    const float* Wih1b = (const float*)d_in[14];
    const float* Whh1b = (const float*)d_in[15];
    const float* bih1b = (const float*)d_in[16];
    const float* bhh1b = (const float*)d_in[17];
    const float* Wout  = (const float*)d_in[18];
    const float* bout  = (const float*)d_in[19];

    static bool attr_set = false;
    if (!attr_set) {
        cudaFuncSetAttribute(gates1_gemm_kernel,
                             cudaFuncAttributeMaxDynamicSharedMemorySize, GEMM_SMEM);
        attr_set = true;
    }

    lstm_l0_kernel<<<256, 256>>>(x, lens,
                                 Wih0f, Whh0f, bih0f, bhh0f,
                                 Wih0b, Whh0b, bih0b, bhh0b);

    dim3 gg(TQ / GM_ROWS, BQ, 2);
    gates1_gemm_kernel<<<gg, 256, GEMM_SMEM>>>(lens, Wih1f, Wih1b,
                                               bih1f, bhh1f, bih1b, bhh1b);

    lstm_l1_kernel<<<256, 256>>>(lens, Whh1f, Whh1b);

    dim3 gf(BQ / FB, 4);
    final_kernel<<<gf, 256>>>(Wout, bout, (float*)d_out);
}